// round 2
// baseline (speedup 1.0000x reference)
#include <cuda_runtime.h>
#include <cstdint>

// ---------------------------------------------------------------------------
// Problem constants
// ---------------------------------------------------------------------------
#define BB   4
#define SS   2048
#define DIM  1024
#define HH   16
#define HD   64
#define MB   16
#define NMB  128           // S / MB
#define NB   11            // CP + DEG
#define NKNOTS 15
#define EPSV 1e-6f

// ---------------------------------------------------------------------------
// Device scratch (no cudaMalloc allowed)
// ---------------------------------------------------------------------------
__device__ float g_Q[(size_t)BB * HH * SS * HD];   // (b,h,s,d)
__device__ float g_K[(size_t)BB * HH * SS * HD];
__device__ float g_V[(size_t)BB * HH * SS * HD];
__device__ float g_Y[(size_t)BB * SS * DIM];       // (b,s,dim)
__device__ float g_N[(size_t)BB * SS * DIM];       // normalized
__device__ float g_eta[(size_t)BB * HH * NMB * MB];
__device__ float g_cos[SS * (HD / 2)];
__device__ float g_sin[SS * (HD / 2)];

// ---------------------------------------------------------------------------
// Helpers
// ---------------------------------------------------------------------------
__device__ __forceinline__ void wsum2(float &a, float &b) {
#pragma unroll
    for (int o = 16; o > 0; o >>= 1) {
        a += __shfl_xor_sync(0xffffffffu, a, o);
        b += __shfl_xor_sync(0xffffffffu, b, o);
    }
}

// B-spline basis (degree 3, 15 knots -> 11 basis values), faithful to reference
__device__ __forceinline__ void bspline11(float x, const float *__restrict__ kn,
                                          float *__restrict__ out) {
    float b[14];
#pragma unroll
    for (int j = 0; j < 14; j++)
        b[j] = (x >= kn[j] && x < kn[j + 1]) ? 1.0f : 0.0f;
#pragma unroll
    for (int k = 1; k <= 3; k++) {
#pragma unroll
        for (int j = 0; j < 13; j++) {
            if (j < 14 - k) {
                float l = (x - kn[j]) / (kn[j + k] - kn[j]);
                float r = (kn[j + k + 1] - x) / (kn[j + k + 1] - kn[j + 1]);
                b[j] = l * b[j] + r * b[j + 1];
            }
        }
    }
#pragma unroll
    for (int j = 0; j < NB; j++) out[j] = b[j];
}

// ---------------------------------------------------------------------------
// RoPE table: double-precision cos/sin of the fp32 angles (trig-accuracy safe)
// ---------------------------------------------------------------------------
__global__ void rope_tab_kernel(const float *__restrict__ posf) {
    int i = blockIdx.x * blockDim.x + threadIdx.x;
    if (i < SS * (HD / 2)) {
        double a = (double)posf[i];
        g_cos[i] = (float)cos(a);
        g_sin[i] = (float)sin(a);
    }
}

// ---------------------------------------------------------------------------
// fp32 SGEMM core: C(MxN) = A(MxK) * W(NxK)^T ; BM=BN=128, BK=8, 256 threads
// ---------------------------------------------------------------------------
__device__ __forceinline__ void sgemm_core(const float *__restrict__ A,
                                           const float *__restrict__ W,
                                           float *As, float *Bs,
                                           float (&acc)[8][8],
                                           int rowBase, int colBase) {
    int tid = threadIdx.x;
    int lrow = tid >> 1;
    int kq = (tid & 1) * 4;
    const float *Ap = A + (size_t)(rowBase + lrow) * 1024 + kq;
    const float *Wp = W + (size_t)(colBase + lrow) * 1024 + kq;
    int tx = tid & 15, ty = tid >> 4;

    for (int k0 = 0; k0 < 1024; k0 += 8) {
        float4 av = *(const float4 *)(Ap + k0);
        float4 wv = *(const float4 *)(Wp + k0);
        __syncthreads();
        As[(kq + 0) * 128 + lrow] = av.x;
        As[(kq + 1) * 128 + lrow] = av.y;
        As[(kq + 2) * 128 + lrow] = av.z;
        As[(kq + 3) * 128 + lrow] = av.w;
        Bs[(kq + 0) * 128 + lrow] = wv.x;
        Bs[(kq + 1) * 128 + lrow] = wv.y;
        Bs[(kq + 2) * 128 + lrow] = wv.z;
        Bs[(kq + 3) * 128 + lrow] = wv.w;
        __syncthreads();
#pragma unroll
        for (int kk = 0; kk < 8; kk++) {
            float4 a0 = *(const float4 *)&As[kk * 128 + ty * 8];
            float4 a1 = *(const float4 *)&As[kk * 128 + ty * 8 + 4];
            float4 b0 = *(const float4 *)&Bs[kk * 128 + tx * 8];
            float4 b1 = *(const float4 *)&Bs[kk * 128 + tx * 8 + 4];
            float ar[8] = {a0.x, a0.y, a0.z, a0.w, a1.x, a1.y, a1.z, a1.w};
            float br[8] = {b0.x, b0.y, b0.z, b0.w, b1.x, b1.y, b1.z, b1.w};
#pragma unroll
            for (int i = 0; i < 8; i++)
#pragma unroll
                for (int j = 0; j < 8; j++)
                    acc[i][j] = fmaf(ar[i], br[j], acc[i][j]);
        }
    }
}

// QKV projection + RoPE, scattering into (b,h,s,d) layout. blockIdx.z in {0,1,2}
__global__ __launch_bounds__(256) void sgemm_qkv_kernel(
    const float *__restrict__ x, const float *__restrict__ Wq,
    const float *__restrict__ Wk, const float *__restrict__ Wv) {
    __shared__ float As[8 * 128];
    __shared__ float Bs[8 * 128];
    const float *W = (blockIdx.z == 0) ? Wq : (blockIdx.z == 1) ? Wk : Wv;
    float *O = (blockIdx.z == 0) ? g_Q : (blockIdx.z == 1) ? g_K : g_V;

    float acc[8][8];
#pragma unroll
    for (int i = 0; i < 8; i++)
#pragma unroll
        for (int j = 0; j < 8; j++) acc[i][j] = 0.f;

    int rowBase = blockIdx.y * 128, colBase = blockIdx.x * 128;
    sgemm_core(x, W, As, Bs, acc, rowBase, colBase);

    int tx = threadIdx.x & 15, ty = threadIdx.x >> 4;
#pragma unroll
    for (int i = 0; i < 8; i++) {
        int r = rowBase + ty * 8 + i;
        int b = r >> 11;          // S = 2048
        int s = r & 2047;
#pragma unroll
        for (int j = 0; j < 8; j += 2) {
            int c = colBase + tx * 8 + j;
            int h = c >> 6;
            int dd = c & 63;
            int jj = dd >> 1;
            float cs = g_cos[s * 32 + jj];
            float sn = g_sin[s * 32 + jj];
            float t1 = acc[i][j], t2 = acc[i][j + 1];
            size_t o = (((size_t)(b * HH + h) * SS) + s) * HD + dd;
            O[o]     = t1 * cs - t2 * sn;
            O[o + 1] = t1 * sn + t2 * cs;
        }
    }
}

// Final projection: d_out = g_N @ Wo^T (plain row-major)
__global__ __launch_bounds__(256) void sgemm_out_kernel(
    const float *__restrict__ Wo, float *__restrict__ out) {
    __shared__ float As[8 * 128];
    __shared__ float Bs[8 * 128];
    float acc[8][8];
#pragma unroll
    for (int i = 0; i < 8; i++)
#pragma unroll
        for (int j = 0; j < 8; j++) acc[i][j] = 0.f;

    int rowBase = blockIdx.y * 128, colBase = blockIdx.x * 128;
    sgemm_core(g_N, Wo, As, Bs, acc, rowBase, colBase);

    int tx = threadIdx.x & 15, ty = threadIdx.x >> 4;
#pragma unroll
    for (int i = 0; i < 8; i++) {
        size_t r = rowBase + ty * 8 + i;
#pragma unroll
        for (int j = 0; j < 8; j++) {
            int c = colBase + tx * 8 + j;
            out[r * 1024 + c] = acc[i][j];
        }
    }
}

// ---------------------------------------------------------------------------
// eta = BASE_LR * sigmoid(x . lr_W[h] + lr_b[h]) / HD * gs[m]
// one block per token row, 128 threads
// ---------------------------------------------------------------------------
__global__ __launch_bounds__(128) void eta_kernel(
    const float *__restrict__ x, const float *__restrict__ lrW,
    const float *__restrict__ lrb, const float *__restrict__ gsc) {
    int row = blockIdx.x;  // b*2048 + s
    __shared__ float xs[1024];
    const float4 *xp = (const float4 *)(x + (size_t)row * 1024);
    float4 *xsp = (float4 *)xs;
    xsp[threadIdx.x] = xp[threadIdx.x];
    xsp[threadIdx.x + 128] = xp[threadIdx.x + 128];
    __syncthreads();

    int w = threadIdx.x >> 5, l = threadIdx.x & 31;
    int b = row >> 11, s = row & 2047;
    int n = s >> 4, m = s & 15;
    float gs = fmaxf(1.0f / (float)(m + 1) + gsc[m], 0.0f);

#pragma unroll
    for (int hh = 0; hh < 4; hh++) {
        int h = w * 4 + hh;
        const float *wp = lrW + (size_t)h * 1024;
        float sum = 0.f;
        for (int k = l; k < 1024; k += 32) sum = fmaf(xs[k], wp[k], sum);
#pragma unroll
        for (int o = 16; o > 0; o >>= 1) sum += __shfl_xor_sync(0xffffffffu, sum, o);
        if (l == 0) {
            float lr = 1.0f / (1.0f + expf(-(sum + lrb[h]))) * (1.0f / 64.0f);
            g_eta[(((size_t)b * HH + h) * NMB + n) * MB + m] = lr * gs;
        }
    }
}

// ---------------------------------------------------------------------------
// Sequential TTT scan: one CTA per (b,h), 512 threads (warp=m, lane covers d,d+32)
// ---------------------------------------------------------------------------
__global__ __launch_bounds__(512) void scan_kernel(
    const float *__restrict__ gamma, const float *__restrict__ beta,
    const float *__restrict__ knots, const float *__restrict__ coeff) {
    __shared__ float Ws[NB * HD];           // 2816 B
    __shared__ float tokbuf[MB * NB * HD];  // 45056 B

    int bh = blockIdx.x;
    int b = bh >> 4, h = bh & 15;
    int tid = threadIdx.x, m = tid >> 5, l = tid & 31;

    float kn[NKNOTS];
#pragma unroll
    for (int j = 0; j < NKNOTS; j++) kn[j] = knots[j];

    float g0 = gamma[h * HD + l], g1 = gamma[h * HD + l + 32];
    float be0 = beta[h * HD + l], be1 = beta[h * HD + l + 32];

    for (int idx = tid; idx < NB * HD; idx += 512)
        Ws[idx] = coeff[(size_t)h * NB * HD + idx];

    const float *Qb = g_Q + (size_t)bh * SS * HD;
    const float *Kb = g_K + (size_t)bh * SS * HD;
    const float *Vb = g_V + (size_t)bh * SS * HD;
    const float *eb = g_eta + (size_t)bh * NMB * MB;
    float *Yb = g_Y + (size_t)b * SS * DIM + h * HD;
    __syncthreads();

    for (int n = 0; n < NMB; n++) {
        int base = (n * MB + m) * HD + l;
        float q0 = Qb[base], q1 = Qb[base + 32];
        float k0 = Kb[base], k1 = Kb[base + 32];
        float v0 = Vb[base], v1 = Vb[base + 32];
        float e = eb[n * MB + m];

        float bk0[NB], bk1[NB];
        bspline11(k0, kn, bk0);
        bspline11(k1, kn, bk1);

        float z0 = k0 / (1.0f + expf(-k0));
        float z1 = k1 / (1.0f + expf(-k1));
#pragma unroll
        for (int j = 0; j < NB; j++) {
            z0 = fmaf(bk0[j], Ws[j * HD + l], z0);
            z1 = fmaf(bk1[j], Ws[j * HD + l + 32], z1);
        }
        // ln_fused_l2_bwd (row over 64 dims = 1 warp, 2 vals/lane)
        float s1 = z0 + z1, s2 = fmaf(z0, z0, z1 * z1);
        wsum2(s1, s2);
        float mu = s1 * (1.f / 64.f);
        float var = s2 * (1.f / 64.f) - mu * mu;
        float rstd = rsqrtf(var + EPSV);
        float xh0 = (z0 - mu) * rstd, xh1 = (z1 - mu) * rstd;
        float gh0 = (fmaf(g0, xh0, be0) - (v0 - k0)) * g0;
        float gh1 = (fmaf(g1, xh1, be1) - (v1 - k1)) * g1;
        s1 = gh0 + gh1;
        s2 = fmaf(gh0, xh0, gh1 * xh1);
        wsum2(s1, s2);
        float mg = s1 * (1.f / 64.f), mgx = s2 * (1.f / 64.f);
        float gz0 = (gh0 - mg - xh0 * mgx) * rstd;
        float gz1 = (gh1 - mg - xh1 * mgx) * rstd;

        float eg0 = e * gz0, eg1 = e * gz1;
#pragma unroll
        for (int j = 0; j < NB; j++) {
            tokbuf[(m * NB + j) * HD + l]      = eg0 * bk0[j];
            tokbuf[(m * NB + j) * HD + l + 32] = eg1 * bk1[j];
        }
        __syncthreads();

        // inclusive cumsum over m (16) for all 704 (j,d) pairs
        for (int idx = tid; idx < NB * HD; idx += 512) {
            float acc = 0.f;
#pragma unroll
            for (int mm = 0; mm < MB; mm++) {
                acc += tokbuf[mm * (NB * HD) + idx];
                tokbuf[mm * (NB * HD) + idx] = acc;
            }
        }
        __syncthreads();

        float bq0[NB], bq1[NB];
        bspline11(q0, kn, bq0);
        bspline11(q1, kn, bq1);
        float zq0 = q0 / (1.0f + expf(-q0));
        float zq1 = q1 / (1.0f + expf(-q1));
#pragma unroll
        for (int j = 0; j < NB; j++) {
            zq0 = fmaf(bq0[j], Ws[j * HD + l] - tokbuf[(m * NB + j) * HD + l], zq0);
            zq1 = fmaf(bq1[j], Ws[j * HD + l + 32] - tokbuf[(m * NB + j) * HD + l + 32], zq1);
        }
        // ln_fwd
        s1 = zq0 + zq1;
        s2 = fmaf(zq0, zq0, zq1 * zq1);
        wsum2(s1, s2);
        mu = s1 * (1.f / 64.f);
        var = s2 * (1.f / 64.f) - mu * mu;
        rstd = rsqrtf(var + EPSV);
        float y0 = q0 + fmaf(g0, (zq0 - mu) * rstd, be0);
        float y1 = q1 + fmaf(g1, (zq1 - mu) * rstd, be1);

        size_t yo = (size_t)(n * MB + m) * DIM;
        Yb[yo + l] = y0;
        Yb[yo + l + 32] = y1;

        __syncthreads();  // all Ws reads done before update
        for (int idx = tid; idx < NB * HD; idx += 512)
            Ws[idx] -= tokbuf[15 * (NB * HD) + idx];
        __syncthreads();
    }
}

// ---------------------------------------------------------------------------
// Final layernorm over DIM, writes g_N
// ---------------------------------------------------------------------------
__global__ __launch_bounds__(256) void ln_kernel(const float *__restrict__ pw,
                                                 const float *__restrict__ pb) {
    int row = blockIdx.x;
    int tid = threadIdx.x;
    float4 v = *((const float4 *)(g_Y + (size_t)row * 1024) + tid);
    float s1 = v.x + v.y + v.z + v.w;
    float s2 = v.x * v.x + v.y * v.y + v.z * v.z + v.w * v.w;
    wsum2(s1, s2);
    __shared__ float sa[8], sb[8];
    int w = tid >> 5, l = tid & 31;
    if (l == 0) { sa[w] = s1; sb[w] = s2; }
    __syncthreads();
    s1 = 0.f; s2 = 0.f;
#pragma unroll
    for (int i = 0; i < 8; i++) { s1 += sa[i]; s2 += sb[i]; }
    float mu = s1 * (1.f / 1024.f);
    float var = s2 * (1.f / 1024.f) - mu * mu;
    float rstd = rsqrtf(var + EPSV);
    float4 pwv = *((const float4 *)pw + tid);
    float4 pbv = *((const float4 *)pb + tid);
    float4 o;
    o.x = (v.x - mu) * rstd * pwv.x + pbv.x;
    o.y = (v.y - mu) * rstd * pwv.y + pbv.y;
    o.z = (v.z - mu) * rstd * pwv.z + pbv.z;
    o.w = (v.w - mu) * rstd * pwv.w + pbv.w;
    *((float4 *)(g_N + (size_t)row * 1024) + tid) = o;
}

// ---------------------------------------------------------------------------
// Launch
// ---------------------------------------------------------------------------
extern "C" void kernel_launch(void *const *d_in, const int *in_sizes, int n_in,
                              void *d_out, int out_size) {
    const float *x     = (const float *)d_in[0];
    const float *posf  = (const float *)d_in[1];
    const float *Wq    = (const float *)d_in[2];
    const float *Wk    = (const float *)d_in[3];
    const float *Wv    = (const float *)d_in[4];
    const float *Wo    = (const float *)d_in[5];
    const float *lrW   = (const float *)d_in[6];
    const float *lrb   = (const float *)d_in[7];
    const float *gsc   = (const float *)d_in[8];
    const float *tgam  = (const float *)d_in[9];
    const float *tbet  = (const float *)d_in[10];
    const float *postw = (const float *)d_in[11];
    const float *postb = (const float *)d_in[12];
    const float *coeff = (const float *)d_in[13];
    const float *knots = (const float *)d_in[14];
    float *out = (float *)d_out;

    rope_tab_kernel<<<(SS * (HD / 2) + 1023) / 1024, 1024>>>(posf);
    sgemm_qkv_kernel<<<dim3(DIM / 128, BB * SS / 128, 3), 256>>>(x, Wq, Wk, Wv);
    eta_kernel<<<BB * SS, 128>>>(x, lrW, lrb, gsc);
    scan_kernel<<<BB * HH, 512>>>(tgam, tbet, knots, coeff);
    ln_kernel<<<BB * SS, 256>>>(postw, postb);
    sgemm_out_kernel<<<dim3(DIM / 128, BB * SS / 128, 1), 256>>>(Wo, out);
}

// round 3
// speedup vs baseline: 1.0627x; 1.0627x over previous
#include <cuda_runtime.h>
#include <cstdint>

// ---------------------------------------------------------------------------
// Problem constants
// ---------------------------------------------------------------------------
#define BB   4
#define SS   2048
#define DIM  1024
#define HH   16
#define HD   64
#define MB   16
#define NMB  128           // S / MB
#define NB   11            // CP + DEG
#define NKNOTS 15
#define EPSV 1e-6f

// ---------------------------------------------------------------------------
// Device scratch (no cudaMalloc allowed)
// ---------------------------------------------------------------------------
__device__ float g_Q[(size_t)BB * HH * SS * HD];   // (b,h,s,d)
__device__ float g_K[(size_t)BB * HH * SS * HD];
__device__ float g_V[(size_t)BB * HH * SS * HD];
__device__ float g_Y[(size_t)BB * SS * DIM];       // (b,s,dim)
__device__ float g_N[(size_t)BB * SS * DIM];       // normalized
__device__ float g_eta[(size_t)BB * HH * NMB * MB];
__device__ float g_cos[SS * (HD / 2)];
__device__ float g_sin[SS * (HD / 2)];

// ---------------------------------------------------------------------------
// Helpers
// ---------------------------------------------------------------------------
__device__ __forceinline__ void wsum2(float &a, float &b) {
#pragma unroll
    for (int o = 16; o > 0; o >>= 1) {
        a += __shfl_xor_sync(0xffffffffu, a, o);
        b += __shfl_xor_sync(0xffffffffu, b, o);
    }
}

__device__ __forceinline__ uint32_t f2tf32(float x) {
    uint32_t r;
    asm("cvt.rna.tf32.f32 %0, %1;" : "=r"(r) : "f"(x));
    return r;
}

__device__ __forceinline__ void split_tf32(float x, uint32_t &h, uint32_t &l) {
    h = f2tf32(x);
    l = f2tf32(x - __uint_as_float(h));
}

__device__ __forceinline__ void mma_tf32(float *d, const uint32_t *a,
                                         const uint32_t *b) {
    asm volatile(
        "mma.sync.aligned.m16n8k8.row.col.f32.tf32.tf32.f32 "
        "{%0,%1,%2,%3}, {%4,%5,%6,%7}, {%8,%9}, {%0,%1,%2,%3};\n"
        : "+f"(d[0]), "+f"(d[1]), "+f"(d[2]), "+f"(d[3])
        : "r"(a[0]), "r"(a[1]), "r"(a[2]), "r"(a[3]), "r"(b[0]), "r"(b[1]));
}

// B-spline basis (degree 3, 15 knots -> 11 basis values), faithful to reference
__device__ __forceinline__ void bspline11(float x, const float *__restrict__ kn,
                                          float *__restrict__ out) {
    float b[14];
#pragma unroll
    for (int j = 0; j < 14; j++)
        b[j] = (x >= kn[j] && x < kn[j + 1]) ? 1.0f : 0.0f;
#pragma unroll
    for (int k = 1; k <= 3; k++) {
#pragma unroll
        for (int j = 0; j < 13; j++) {
            if (j < 14 - k) {
                float l = (x - kn[j]) / (kn[j + k] - kn[j]);
                float r = (kn[j + k + 1] - x) / (kn[j + k + 1] - kn[j + 1]);
                b[j] = l * b[j] + r * b[j + 1];
            }
        }
    }
#pragma unroll
    for (int j = 0; j < NB; j++) out[j] = b[j];
}

// ---------------------------------------------------------------------------
// RoPE table: double-precision cos/sin of the fp32 angles (trig-accuracy safe)
// ---------------------------------------------------------------------------
__global__ void rope_tab_kernel(const float *__restrict__ posf) {
    int i = blockIdx.x * blockDim.x + threadIdx.x;
    if (i < SS * (HD / 2)) {
        double a = (double)posf[i];
        g_cos[i] = (float)cos(a);
        g_sin[i] = (float)sin(a);
    }
}

// ---------------------------------------------------------------------------
// 3xTF32 tensor-core GEMM core: C(128x128) = A(128xK) * W(128xK)^T
// 256 threads = 8 warps in 2(M) x 4(N); warp tile 64x32; mma m16n8k8
// ---------------------------------------------------------------------------
#define TBK 16
#define SPITCH 17   // smem row pitch (floats)

__device__ __forceinline__ void store_split(uint32_t *H, uint32_t *L, int idx,
                                            float4 v) {
    split_tf32(v.x, H[idx + 0], L[idx + 0]);
    split_tf32(v.y, H[idx + 1], L[idx + 1]);
    split_tf32(v.z, H[idx + 2], L[idx + 2]);
    split_tf32(v.w, H[idx + 3], L[idx + 3]);
}

__device__ __forceinline__ void tc_gemm_core(
    const float *__restrict__ A, const float *__restrict__ W,
    uint32_t *AsH, uint32_t *AsL, uint32_t *BsH, uint32_t *BsL,
    float (&acc)[4][4][4], int rowBase, int colBase) {
    int tid = threadIdx.x;
    int lane = tid & 31, wid = tid >> 5;
    int wm = wid >> 2, wn = wid & 3;
    int r0 = tid >> 2, c4 = (tid & 3) << 2;

    const float *Ap = A + (size_t)(rowBase + r0) * 1024 + c4;
    const float *Wp = W + (size_t)(colBase + r0) * 1024 + c4;

    for (int k0 = 0; k0 < 1024; k0 += TBK) {
        float4 av0 = *(const float4 *)(Ap + k0);
        float4 av1 = *(const float4 *)(Ap + (size_t)64 * 1024 + k0);
        float4 wv0 = *(const float4 *)(Wp + k0);
        float4 wv1 = *(const float4 *)(Wp + (size_t)64 * 1024 + k0);
        __syncthreads();
        store_split(AsH, AsL, r0 * SPITCH + c4, av0);
        store_split(AsH, AsL, (r0 + 64) * SPITCH + c4, av1);
        store_split(BsH, BsL, r0 * SPITCH + c4, wv0);
        store_split(BsH, BsL, (r0 + 64) * SPITCH + c4, wv1);
        __syncthreads();
#pragma unroll
        for (int ks = 0; ks < 2; ks++) {
            int kb = ks * 8 + (lane & 3);
            uint32_t ah[4][4], al[4][4], bh[4][2], bl[4][2];
#pragma unroll
            for (int mt = 0; mt < 4; mt++) {
                int row = wm * 64 + mt * 16 + (lane >> 2);
                ah[mt][0] = AsH[row * SPITCH + kb];
                ah[mt][1] = AsH[(row + 8) * SPITCH + kb];
                ah[mt][2] = AsH[row * SPITCH + kb + 4];
                ah[mt][3] = AsH[(row + 8) * SPITCH + kb + 4];
                al[mt][0] = AsL[row * SPITCH + kb];
                al[mt][1] = AsL[(row + 8) * SPITCH + kb];
                al[mt][2] = AsL[row * SPITCH + kb + 4];
                al[mt][3] = AsL[(row + 8) * SPITCH + kb + 4];
            }
#pragma unroll
            for (int nt = 0; nt < 4; nt++) {
                int col = wn * 32 + nt * 8 + (lane >> 2);
                bh[nt][0] = BsH[col * SPITCH + kb];
                bh[nt][1] = BsH[col * SPITCH + kb + 4];
                bl[nt][0] = BsL[col * SPITCH + kb];
                bl[nt][1] = BsL[col * SPITCH + kb + 4];
            }
#pragma unroll
            for (int mt = 0; mt < 4; mt++)
#pragma unroll
                for (int nt = 0; nt < 4; nt++) {
                    mma_tf32(acc[mt][nt], ah[mt], bh[nt]);
                    mma_tf32(acc[mt][nt], al[mt], bh[nt]);
                    mma_tf32(acc[mt][nt], ah[mt], bl[nt]);
                }
        }
    }
}

// QKV projection + RoPE, scattering into (b,h,s,d) layout. blockIdx.z in {0,1,2}
__global__ __launch_bounds__(256) void tc_qkv_kernel(
    const float *__restrict__ x, const float *__restrict__ Wq,
    const float *__restrict__ Wk, const float *__restrict__ Wv) {
    __shared__ uint32_t AsH[128 * SPITCH], AsL[128 * SPITCH];
    __shared__ uint32_t BsH[128 * SPITCH], BsL[128 * SPITCH];
    const float *W = (blockIdx.z == 0) ? Wq : (blockIdx.z == 1) ? Wk : Wv;
    float *O = (blockIdx.z == 0) ? g_Q : (blockIdx.z == 1) ? g_K : g_V;

    float acc[4][4][4];
#pragma unroll
    for (int a = 0; a < 4; a++)
#pragma unroll
        for (int b = 0; b < 4; b++)
#pragma unroll
            for (int c = 0; c < 4; c++) acc[a][b][c] = 0.f;

    int rowBase = blockIdx.y * 128, colBase = blockIdx.x * 128;
    tc_gemm_core(x, W, AsH, AsL, BsH, BsL, acc, rowBase, colBase);

    int lane = threadIdx.x & 31, wid = threadIdx.x >> 5;
    int wm = wid >> 2, wn = wid & 3;
#pragma unroll
    for (int mt = 0; mt < 4; mt++) {
        int r = rowBase + wm * 64 + mt * 16 + (lane >> 2);
#pragma unroll
        for (int half = 0; half < 2; half++) {
            int ri = r + half * 8;
            int b = ri >> 11;  // S = 2048
            int s = ri & 2047;
#pragma unroll
            for (int nt = 0; nt < 4; nt++) {
                int c = colBase + wn * 32 + nt * 8 + 2 * (lane & 3);
                int h = c >> 6;
                int dd = c & 63;
                int jj = dd >> 1;
                float cs = g_cos[s * 32 + jj];
                float sn = g_sin[s * 32 + jj];
                float t1 = acc[mt][nt][2 * half];
                float t2 = acc[mt][nt][2 * half + 1];
                size_t o = (((size_t)(b * HH + h) * SS) + s) * HD + dd;
                O[o]     = t1 * cs - t2 * sn;
                O[o + 1] = t1 * sn + t2 * cs;
            }
        }
    }
}

// Final projection: d_out = g_N @ Wo^T (plain row-major)
__global__ __launch_bounds__(256) void tc_out_kernel(
    const float *__restrict__ Wo, float *__restrict__ out) {
    __shared__ uint32_t AsH[128 * SPITCH], AsL[128 * SPITCH];
    __shared__ uint32_t BsH[128 * SPITCH], BsL[128 * SPITCH];
    float acc[4][4][4];
#pragma unroll
    for (int a = 0; a < 4; a++)
#pragma unroll
        for (int b = 0; b < 4; b++)
#pragma unroll
            for (int c = 0; c < 4; c++) acc[a][b][c] = 0.f;

    int rowBase = blockIdx.y * 128, colBase = blockIdx.x * 128;
    tc_gemm_core(g_N, Wo, AsH, AsL, BsH, BsL, acc, rowBase, colBase);

    int lane = threadIdx.x & 31, wid = threadIdx.x >> 5;
    int wm = wid >> 2, wn = wid & 3;
#pragma unroll
    for (int mt = 0; mt < 4; mt++) {
        int r = rowBase + wm * 64 + mt * 16 + (lane >> 2);
#pragma unroll
        for (int half = 0; half < 2; half++) {
            size_t ri = r + half * 8;
#pragma unroll
            for (int nt = 0; nt < 4; nt++) {
                int c = colBase + wn * 32 + nt * 8 + 2 * (lane & 3);
                float2 v = make_float2(acc[mt][nt][2 * half],
                                       acc[mt][nt][2 * half + 1]);
                *(float2 *)(out + ri * 1024 + c) = v;
            }
        }
    }
}

// ---------------------------------------------------------------------------
// eta = BASE_LR * sigmoid(x . lr_W[h] + lr_b[h]) / HD * gs[m]
// ---------------------------------------------------------------------------
__global__ __launch_bounds__(128) void eta_kernel(
    const float *__restrict__ x, const float *__restrict__ lrW,
    const float *__restrict__ lrb, const float *__restrict__ gsc) {
    int row = blockIdx.x;  // b*2048 + s
    __shared__ float xs[1024];
    const float4 *xp = (const float4 *)(x + (size_t)row * 1024);
    float4 *xsp = (float4 *)xs;
    xsp[threadIdx.x] = xp[threadIdx.x];
    xsp[threadIdx.x + 128] = xp[threadIdx.x + 128];
    __syncthreads();

    int w = threadIdx.x >> 5, l = threadIdx.x & 31;
    int b = row >> 11, s = row & 2047;
    int n = s >> 4, m = s & 15;
    float gs = fmaxf(1.0f / (float)(m + 1) + gsc[m], 0.0f);

#pragma unroll
    for (int hh = 0; hh < 4; hh++) {
        int h = w * 4 + hh;
        const float *wp = lrW + (size_t)h * 1024;
        float sum = 0.f;
        for (int k = l; k < 1024; k += 32) sum = fmaf(xs[k], wp[k], sum);
#pragma unroll
        for (int o = 16; o > 0; o >>= 1) sum += __shfl_xor_sync(0xffffffffu, sum, o);
        if (l == 0) {
            float lr = 1.0f / (1.0f + expf(-(sum + lrb[h]))) * (1.0f / 64.0f);
            g_eta[(((size_t)b * HH + h) * NMB + n) * MB + m] = lr * gs;
        }
    }
}

// ---------------------------------------------------------------------------
// Sequential TTT scan: one CTA per (b,h), 512 threads (warp=m, lane covers d,d+32)
// ---------------------------------------------------------------------------
__global__ __launch_bounds__(512) void scan_kernel(
    const float *__restrict__ gamma, const float *__restrict__ beta,
    const float *__restrict__ knots, const float *__restrict__ coeff) {
    __shared__ float Ws[NB * HD];           // 2816 B
    __shared__ float tokbuf[MB * NB * HD];  // 45056 B

    int bh = blockIdx.x;
    int b = bh >> 4, h = bh & 15;
    int tid = threadIdx.x, m = tid >> 5, l = tid & 31;

    float kn[NKNOTS];
#pragma unroll
    for (int j = 0; j < NKNOTS; j++) kn[j] = knots[j];

    float g0 = gamma[h * HD + l], g1 = gamma[h * HD + l + 32];
    float be0 = beta[h * HD + l], be1 = beta[h * HD + l + 32];

    for (int idx = tid; idx < NB * HD; idx += 512)
        Ws[idx] = coeff[(size_t)h * NB * HD + idx];

    const float *Qb = g_Q + (size_t)bh * SS * HD;
    const float *Kb = g_K + (size_t)bh * SS * HD;
    const float *Vb = g_V + (size_t)bh * SS * HD;
    const float *eb = g_eta + (size_t)bh * NMB * MB;
    float *Yb = g_Y + (size_t)b * SS * DIM + h * HD;
    __syncthreads();

    for (int n = 0; n < NMB; n++) {
        int base = (n * MB + m) * HD + l;
        float q0 = Qb[base], q1 = Qb[base + 32];
        float k0 = Kb[base], k1 = Kb[base + 32];
        float v0 = Vb[base], v1 = Vb[base + 32];
        float e = eb[n * MB + m];

        float bk0[NB], bk1[NB];
        bspline11(k0, kn, bk0);
        bspline11(k1, kn, bk1);

        float z0 = k0 / (1.0f + expf(-k0));
        float z1 = k1 / (1.0f + expf(-k1));
#pragma unroll
        for (int j = 0; j < NB; j++) {
            z0 = fmaf(bk0[j], Ws[j * HD + l], z0);
            z1 = fmaf(bk1[j], Ws[j * HD + l + 32], z1);
        }
        float s1 = z0 + z1, s2 = fmaf(z0, z0, z1 * z1);
        wsum2(s1, s2);
        float mu = s1 * (1.f / 64.f);
        float var = s2 * (1.f / 64.f) - mu * mu;
        float rstd = rsqrtf(var + EPSV);
        float xh0 = (z0 - mu) * rstd, xh1 = (z1 - mu) * rstd;
        float gh0 = (fmaf(g0, xh0, be0) - (v0 - k0)) * g0;
        float gh1 = (fmaf(g1, xh1, be1) - (v1 - k1)) * g1;
        s1 = gh0 + gh1;
        s2 = fmaf(gh0, xh0, gh1 * xh1);
        wsum2(s1, s2);
        float mg = s1 * (1.f / 64.f), mgx = s2 * (1.f / 64.f);
        float gz0 = (gh0 - mg - xh0 * mgx) * rstd;
        float gz1 = (gh1 - mg - xh1 * mgx) * rstd;

        float eg0 = e * gz0, eg1 = e * gz1;
#pragma unroll
        for (int j = 0; j < NB; j++) {
            tokbuf[(m * NB + j) * HD + l]      = eg0 * bk0[j];
            tokbuf[(m * NB + j) * HD + l + 32] = eg1 * bk1[j];
        }
        __syncthreads();

        for (int idx = tid; idx < NB * HD; idx += 512) {
            float acc = 0.f;
#pragma unroll
            for (int mm = 0; mm < MB; mm++) {
                acc += tokbuf[mm * (NB * HD) + idx];
                tokbuf[mm * (NB * HD) + idx] = acc;
            }
        }
        __syncthreads();

        float bq0[NB], bq1[NB];
        bspline11(q0, kn, bq0);
        bspline11(q1, kn, bq1);
        float zq0 = q0 / (1.0f + expf(-q0));
        float zq1 = q1 / (1.0f + expf(-q1));
#pragma unroll
        for (int j = 0; j < NB; j++) {
            zq0 = fmaf(bq0[j], Ws[j * HD + l] - tokbuf[(m * NB + j) * HD + l], zq0);
            zq1 = fmaf(bq1[j], Ws[j * HD + l + 32] - tokbuf[(m * NB + j) * HD + l + 32], zq1);
        }
        s1 = zq0 + zq1;
        s2 = fmaf(zq0, zq0, zq1 * zq1);
        wsum2(s1, s2);
        mu = s1 * (1.f / 64.f);
        var = s2 * (1.f / 64.f) - mu * mu;
        rstd = rsqrtf(var + EPSV);
        float y0 = q0 + fmaf(g0, (zq0 - mu) * rstd, be0);
        float y1 = q1 + fmaf(g1, (zq1 - mu) * rstd, be1);

        size_t yo = (size_t)(n * MB + m) * DIM;
        Yb[yo + l] = y0;
        Yb[yo + l + 32] = y1;

        __syncthreads();
        for (int idx = tid; idx < NB * HD; idx += 512)
            Ws[idx] -= tokbuf[15 * (NB * HD) + idx];
        __syncthreads();
    }
}

// ---------------------------------------------------------------------------
// Final layernorm over DIM, writes g_N
// ---------------------------------------------------------------------------
__global__ __launch_bounds__(256) void ln_kernel(const float *__restrict__ pw,
                                                 const float *__restrict__ pb) {
    int row = blockIdx.x;
    int tid = threadIdx.x;
    float4 v = *((const float4 *)(g_Y + (size_t)row * 1024) + tid);
    float s1 = v.x + v.y + v.z + v.w;
    float s2 = v.x * v.x + v.y * v.y + v.z * v.z + v.w * v.w;
    wsum2(s1, s2);
    __shared__ float sa[8], sb[8];
    int w = tid >> 5, l = tid & 31;
    if (l == 0) { sa[w] = s1; sb[w] = s2; }
    __syncthreads();
    s1 = 0.f; s2 = 0.f;
#pragma unroll
    for (int i = 0; i < 8; i++) { s1 += sa[i]; s2 += sb[i]; }
    float mu = s1 * (1.f / 1024.f);
    float var = s2 * (1.f / 1024.f) - mu * mu;
    float rstd = rsqrtf(var + EPSV);
    float4 pwv = *((const float4 *)pw + tid);
    float4 pbv = *((const float4 *)pb + tid);
    float4 o;
    o.x = (v.x - mu) * rstd * pwv.x + pbv.x;
    o.y = (v.y - mu) * rstd * pwv.y + pbv.y;
    o.z = (v.z - mu) * rstd * pwv.z + pbv.z;
    o.w = (v.w - mu) * rstd * pwv.w + pbv.w;
    *((float4 *)(g_N + (size_t)row * 1024) + tid) = o;
}

// ---------------------------------------------------------------------------
// Launch
// ---------------------------------------------------------------------------
extern "C" void kernel_launch(void *const *d_in, const int *in_sizes, int n_in,
                              void *d_out, int out_size) {
    const float *x     = (const float *)d_in[0];
    const float *posf  = (const float *)d_in[1];
    const float *Wq    = (const float *)d_in[2];
    const float *Wk    = (const float *)d_in[3];
    const float *Wv    = (const float *)d_in[4];
    const float *Wo    = (const float *)d_in[5];
    const float *lrW   = (const float *)d_in[6];
    const float *lrb   = (const float *)d_in[7];
    const float *gsc   = (const float *)d_in[8];
    const float *tgam  = (const float *)d_in[9];
    const float *tbet  = (const float *)d_in[10];
    const float *postw = (const float *)d_in[11];
    const float *postb = (const float *)d_in[12];
    const float *coeff = (const float *)d_in[13];
    const float *knots = (const float *)d_in[14];
    float *out = (float *)d_out;

    rope_tab_kernel<<<(SS * (HD / 2) + 1023) / 1024, 1024>>>(posf);
    tc_qkv_kernel<<<dim3(DIM / 128, BB * SS / 128, 3), 256>>>(x, Wq, Wk, Wv);
    eta_kernel<<<BB * SS, 128>>>(x, lrW, lrb, gsc);
    scan_kernel<<<BB * HH, 512>>>(tgam, tbet, knots, coeff);
    ln_kernel<<<BB * SS, 256>>>(postw, postb);
    tc_out_kernel<<<dim3(DIM / 128, BB * SS / 128, 1), 256>>>(Wo, out);
}

// round 4
// speedup vs baseline: 1.6456x; 1.5485x over previous
#include <cuda_runtime.h>
#include <cstdint>

// ---------------------------------------------------------------------------
// Problem constants
// ---------------------------------------------------------------------------
#define BB   4
#define SS   2048
#define DIM  1024
#define HH   16
#define HD   64
#define MB   16
#define NMB  128           // S / MB
#define NB   11            // CP + DEG
#define NKNOTS 15
#define EPSV 1e-6f

// ---------------------------------------------------------------------------
// Device scratch (no cudaMalloc allowed)
// ---------------------------------------------------------------------------
__device__ float g_Q[(size_t)BB * HH * SS * HD];   // (b,h,s,d)
__device__ float g_K[(size_t)BB * HH * SS * HD];
__device__ float g_V[(size_t)BB * HH * SS * HD];
__device__ float g_Y[(size_t)BB * SS * DIM];       // (b,s,dim)
__device__ float g_eta[(size_t)BB * HH * NMB * MB];
__device__ float g_cos[SS * (HD / 2)];
__device__ float g_sin[SS * (HD / 2)];
// tf32 hi/lo split operands
__device__ uint32_t g_xh[(size_t)BB * SS * DIM];
__device__ uint32_t g_xl[(size_t)BB * SS * DIM];
__device__ uint32_t g_wh[(size_t)4 * DIM * DIM];   // q,k,v,o
__device__ uint32_t g_wl[(size_t)4 * DIM * DIM];
__device__ uint32_t g_nh[(size_t)BB * SS * DIM];
__device__ uint32_t g_nl[(size_t)BB * SS * DIM];

// ---------------------------------------------------------------------------
// Helpers
// ---------------------------------------------------------------------------
__device__ __forceinline__ void wsum2(float &a, float &b) {
#pragma unroll
    for (int o = 16; o > 0; o >>= 1) {
        a += __shfl_xor_sync(0xffffffffu, a, o);
        b += __shfl_xor_sync(0xffffffffu, b, o);
    }
}

__device__ __forceinline__ uint32_t f2tf32(float x) {
    uint32_t r;
    asm("cvt.rna.tf32.f32 %0, %1;" : "=r"(r) : "f"(x));
    return r;
}

__device__ __forceinline__ void split_tf32(float x, uint32_t &h, uint32_t &l) {
    h = f2tf32(x);
    l = f2tf32(x - __uint_as_float(h));
}

__device__ __forceinline__ void mma_tf32(float *d, const uint32_t *a,
                                         const uint32_t *b) {
    asm volatile(
        "mma.sync.aligned.m16n8k8.row.col.f32.tf32.tf32.f32 "
        "{%0,%1,%2,%3}, {%4,%5,%6,%7}, {%8,%9}, {%0,%1,%2,%3};\n"
        : "+f"(d[0]), "+f"(d[1]), "+f"(d[2]), "+f"(d[3])
        : "r"(a[0]), "r"(a[1]), "r"(a[2]), "r"(a[3]), "r"(b[0]), "r"(b[1]));
}

// Uniform-knot cubic B-spline: 11 basis values, zero divisions in the loop.
__device__ __forceinline__ void bspline11u(float x, const float *__restrict__ kn,
                                           float i1, float i2, float i3,
                                           float *__restrict__ out) {
    float b[14];
#pragma unroll
    for (int j = 0; j < 14; j++)
        b[j] = (x >= kn[j] && x < kn[j + 1]) ? 1.0f : 0.0f;
#pragma unroll
    for (int j = 0; j < 13; j++)
        b[j] = ((x - kn[j]) * b[j] + (kn[j + 2] - x) * b[j + 1]) * i1;
#pragma unroll
    for (int j = 0; j < 12; j++)
        b[j] = ((x - kn[j]) * b[j] + (kn[j + 3] - x) * b[j + 1]) * i2;
#pragma unroll
    for (int j = 0; j < 11; j++)
        b[j] = ((x - kn[j]) * b[j] + (kn[j + 4] - x) * b[j + 1]) * i3;
#pragma unroll
    for (int j = 0; j < NB; j++) out[j] = b[j];
}

// ---------------------------------------------------------------------------
// RoPE table: double-precision cos/sin of the fp32 angles
// ---------------------------------------------------------------------------
__global__ void rope_tab_kernel(const float *__restrict__ posf) {
    int i = blockIdx.x * blockDim.x + threadIdx.x;
    if (i < SS * (HD / 2)) {
        double a = (double)posf[i];
        g_cos[i] = (float)cos(a);
        g_sin[i] = (float)sin(a);
    }
}

// ---------------------------------------------------------------------------
// Elementwise tf32 hi/lo split (vectorized)
// ---------------------------------------------------------------------------
__global__ __launch_bounds__(256) void split_kernel(const float4 *__restrict__ src,
                                                    uint4 *__restrict__ hi,
                                                    uint4 *__restrict__ lo, int n4) {
    int i = blockIdx.x * blockDim.x + threadIdx.x;
    if (i < n4) {
        float4 v = src[i];
        uint4 h, l;
        split_tf32(v.x, h.x, l.x);
        split_tf32(v.y, h.y, l.y);
        split_tf32(v.z, h.z, l.z);
        split_tf32(v.w, h.w, l.w);
        hi[i] = h;
        lo[i] = l;
    }
}

// ---------------------------------------------------------------------------
// 3xTF32 tensor-core GEMM core on pre-split operands.
// C(128x128) = A(128xK) * W(128xK)^T ; 256 thr = 8 warps 2(M)x4(N)
// ---------------------------------------------------------------------------
#define SPITCH 20   // smem row pitch (uint32) — 16B-aligned stores, conflict-free

__device__ __forceinline__ void tc_gemm_core(
    const uint32_t *__restrict__ Ah, const uint32_t *__restrict__ Al,
    const uint32_t *__restrict__ Bh, const uint32_t *__restrict__ Bl,
    uint32_t *AsH, uint32_t *AsL, uint32_t *BsH, uint32_t *BsL,
    float (&acc)[4][4][4], int rowBase, int colBase) {
    int tid = threadIdx.x;
    int lane = tid & 31, wid = tid >> 5;
    int wm = wid >> 2, wn = wid & 3;
    int r0 = tid >> 2, c4 = (tid & 3) << 2;

    const uint4 *pAh0 = (const uint4 *)(Ah + (size_t)(rowBase + r0) * 1024 + c4);
    const uint4 *pAl0 = (const uint4 *)(Al + (size_t)(rowBase + r0) * 1024 + c4);
    const uint4 *pBh0 = (const uint4 *)(Bh + (size_t)(colBase + r0) * 1024 + c4);
    const uint4 *pBl0 = (const uint4 *)(Bl + (size_t)(colBase + r0) * 1024 + c4);
    const int rstep = 64 * 1024 / 4;   // +64 rows, in uint4 units

    uint4 vah0, vah1, val0, val1, vbh0, vbh1, vbl0, vbl1;
    // prime k0 = 0
    vah0 = pAh0[0];          vah1 = pAh0[rstep];
    val0 = pAl0[0];          val1 = pAl0[rstep];
    vbh0 = pBh0[0];          vbh1 = pBh0[rstep];
    vbl0 = pBl0[0];          vbl1 = pBl0[rstep];

    for (int k0 = 0; k0 < 1024; k0 += 16) {
        __syncthreads();
        *(uint4 *)&AsH[r0 * SPITCH + c4] = vah0;
        *(uint4 *)&AsH[(r0 + 64) * SPITCH + c4] = vah1;
        *(uint4 *)&AsL[r0 * SPITCH + c4] = val0;
        *(uint4 *)&AsL[(r0 + 64) * SPITCH + c4] = val1;
        *(uint4 *)&BsH[r0 * SPITCH + c4] = vbh0;
        *(uint4 *)&BsH[(r0 + 64) * SPITCH + c4] = vbh1;
        *(uint4 *)&BsL[r0 * SPITCH + c4] = vbl0;
        *(uint4 *)&BsL[(r0 + 64) * SPITCH + c4] = vbl1;
        __syncthreads();
        if (k0 + 16 < 1024) {
            int ko = (k0 + 16) >> 2;
            vah0 = pAh0[ko];          vah1 = pAh0[ko + rstep];
            val0 = pAl0[ko];          val1 = pAl0[ko + rstep];
            vbh0 = pBh0[ko];          vbh1 = pBh0[ko + rstep];
            vbl0 = pBl0[ko];          vbl1 = pBl0[ko + rstep];
        }
#pragma unroll
        for (int ks = 0; ks < 2; ks++) {
            int kb = ks * 8 + (lane & 3);
            uint32_t ah[4][4], al[4][4], bh[4][2], bl[4][2];
#pragma unroll
            for (int mt = 0; mt < 4; mt++) {
                int row = wm * 64 + mt * 16 + (lane >> 2);
                ah[mt][0] = AsH[row * SPITCH + kb];
                ah[mt][1] = AsH[(row + 8) * SPITCH + kb];
                ah[mt][2] = AsH[row * SPITCH + kb + 4];
                ah[mt][3] = AsH[(row + 8) * SPITCH + kb + 4];
                al[mt][0] = AsL[row * SPITCH + kb];
                al[mt][1] = AsL[(row + 8) * SPITCH + kb];
                al[mt][2] = AsL[row * SPITCH + kb + 4];
                al[mt][3] = AsL[(row + 8) * SPITCH + kb + 4];
            }
#pragma unroll
            for (int nt = 0; nt < 4; nt++) {
                int col = wn * 32 + nt * 8 + (lane >> 2);
                bh[nt][0] = BsH[col * SPITCH + kb];
                bh[nt][1] = BsH[col * SPITCH + kb + 4];
                bl[nt][0] = BsL[col * SPITCH + kb];
                bl[nt][1] = BsL[col * SPITCH + kb + 4];
            }
#pragma unroll
            for (int mt = 0; mt < 4; mt++)
#pragma unroll
                for (int nt = 0; nt < 4; nt++) {
                    mma_tf32(acc[mt][nt], ah[mt], bh[nt]);
                    mma_tf32(acc[mt][nt], al[mt], bh[nt]);
                    mma_tf32(acc[mt][nt], ah[mt], bl[nt]);
                }
        }
    }
}

// QKV projection + RoPE, scattering into (b,h,s,d) layout. blockIdx.z in {0,1,2}
__global__ __launch_bounds__(256) void tc_qkv_kernel() {
    __shared__ uint32_t AsH[128 * SPITCH], AsL[128 * SPITCH];
    __shared__ uint32_t BsH[128 * SPITCH], BsL[128 * SPITCH];
    size_t woff = (size_t)blockIdx.z * DIM * DIM;
    float *O = (blockIdx.z == 0) ? g_Q : (blockIdx.z == 1) ? g_K : g_V;

    float acc[4][4][4];
#pragma unroll
    for (int a = 0; a < 4; a++)
#pragma unroll
        for (int b = 0; b < 4; b++)
#pragma unroll
            for (int c = 0; c < 4; c++) acc[a][b][c] = 0.f;

    int rowBase = blockIdx.y * 128, colBase = blockIdx.x * 128;
    tc_gemm_core(g_xh, g_xl, g_wh + woff, g_wl + woff,
                 AsH, AsL, BsH, BsL, acc, rowBase, colBase);

    int lane = threadIdx.x & 31, wid = threadIdx.x >> 5;
    int wm = wid >> 2, wn = wid & 3;
#pragma unroll
    for (int mt = 0; mt < 4; mt++) {
        int r = rowBase + wm * 64 + mt * 16 + (lane >> 2);
#pragma unroll
        for (int half = 0; half < 2; half++) {
            int ri = r + half * 8;
            int b = ri >> 11;  // S = 2048
            int s = ri & 2047;
#pragma unroll
            for (int nt = 0; nt < 4; nt++) {
                int c = colBase + wn * 32 + nt * 8 + 2 * (lane & 3);
                int h = c >> 6;
                int dd = c & 63;
                int jj = dd >> 1;
                float cs = g_cos[s * 32 + jj];
                float sn = g_sin[s * 32 + jj];
                float t1 = acc[mt][nt][2 * half];
                float t2 = acc[mt][nt][2 * half + 1];
                size_t o = (((size_t)(b * HH + h) * SS) + s) * HD + dd;
                O[o]     = t1 * cs - t2 * sn;
                O[o + 1] = t1 * sn + t2 * cs;
            }
        }
    }
}

// Final projection: d_out = N @ Wo^T
__global__ __launch_bounds__(256) void tc_out_kernel(float *__restrict__ out) {
    __shared__ uint32_t AsH[128 * SPITCH], AsL[128 * SPITCH];
    __shared__ uint32_t BsH[128 * SPITCH], BsL[128 * SPITCH];
    float acc[4][4][4];
#pragma unroll
    for (int a = 0; a < 4; a++)
#pragma unroll
        for (int b = 0; b < 4; b++)
#pragma unroll
            for (int c = 0; c < 4; c++) acc[a][b][c] = 0.f;

    int rowBase = blockIdx.y * 128, colBase = blockIdx.x * 128;
    size_t woff = (size_t)3 * DIM * DIM;
    tc_gemm_core(g_nh, g_nl, g_wh + woff, g_wl + woff,
                 AsH, AsL, BsH, BsL, acc, rowBase, colBase);

    int lane = threadIdx.x & 31, wid = threadIdx.x >> 5;
    int wm = wid >> 2, wn = wid & 3;
#pragma unroll
    for (int mt = 0; mt < 4; mt++) {
        int r = rowBase + wm * 64 + mt * 16 + (lane >> 2);
#pragma unroll
        for (int half = 0; half < 2; half++) {
            size_t ri = r + half * 8;
#pragma unroll
            for (int nt = 0; nt < 4; nt++) {
                int c = colBase + wn * 32 + nt * 8 + 2 * (lane & 3);
                float2 v = make_float2(acc[mt][nt][2 * half],
                                       acc[mt][nt][2 * half + 1]);
                *(float2 *)(out + ri * 1024 + c) = v;
            }
        }
    }
}

// ---------------------------------------------------------------------------
// eta = sigmoid(x . lr_W[h] + lr_b[h]) / HD * gs[m]
// ---------------------------------------------------------------------------
__global__ __launch_bounds__(128) void eta_kernel(
    const float *__restrict__ x, const float *__restrict__ lrW,
    const float *__restrict__ lrb, const float *__restrict__ gsc) {
    int row = blockIdx.x;  // b*2048 + s
    __shared__ float xs[1024];
    const float4 *xp = (const float4 *)(x + (size_t)row * 1024);
    float4 *xsp = (float4 *)xs;
    xsp[threadIdx.x] = xp[threadIdx.x];
    xsp[threadIdx.x + 128] = xp[threadIdx.x + 128];
    __syncthreads();

    int w = threadIdx.x >> 5, l = threadIdx.x & 31;
    int b = row >> 11, s = row & 2047;
    int n = s >> 4, m = s & 15;
    float gs = fmaxf(1.0f / (float)(m + 1) + gsc[m], 0.0f);

#pragma unroll
    for (int hh = 0; hh < 4; hh++) {
        int h = w * 4 + hh;
        const float *wp = lrW + (size_t)h * 1024;
        float sum = 0.f;
        for (int k = l; k < 1024; k += 32) sum = fmaf(xs[k], wp[k], sum);
#pragma unroll
        for (int o = 16; o > 0; o >>= 1) sum += __shfl_xor_sync(0xffffffffu, sum, o);
        if (l == 0) {
            float lr = 1.0f / (1.0f + __expf(-(sum + lrb[h]))) * (1.0f / 64.0f);
            g_eta[(((size_t)b * HH + h) * NMB + n) * MB + m] = lr * gs;
        }
    }
}

// ---------------------------------------------------------------------------
// Sequential TTT scan: one CTA per (b,h), 512 threads (warp=m, lane covers d,d+32)
// ---------------------------------------------------------------------------
__global__ __launch_bounds__(512) void scan_kernel(
    const float *__restrict__ gamma, const float *__restrict__ beta,
    const float *__restrict__ knots, const float *__restrict__ coeff) {
    __shared__ float Ws[NB * HD];           // 2816 B
    __shared__ float tokbuf[MB * NB * HD];  // 45056 B

    int bh = blockIdx.x;
    int b = bh >> 4, h = bh & 15;
    int tid = threadIdx.x, m = tid >> 5, l = tid & 31;

    float kn[NKNOTS];
#pragma unroll
    for (int j = 0; j < NKNOTS; j++) kn[j] = knots[j];
    // knots are uniform (linspace): hoist the basis denominators
    float hstep = (kn[NKNOTS - 1] - kn[0]) * (1.0f / (float)(NKNOTS - 1));
    float i1 = 1.0f / hstep;
    float i2 = 0.5f / hstep;
    float i3 = 1.0f / (3.0f * hstep);

    float g0 = gamma[h * HD + l], g1 = gamma[h * HD + l + 32];
    float be0 = beta[h * HD + l], be1 = beta[h * HD + l + 32];

    for (int idx = tid; idx < NB * HD; idx += 512)
        Ws[idx] = coeff[(size_t)h * NB * HD + idx];

    const float *Qb = g_Q + (size_t)bh * SS * HD;
    const float *Kb = g_K + (size_t)bh * SS * HD;
    const float *Vb = g_V + (size_t)bh * SS * HD;
    const float *eb = g_eta + (size_t)bh * NMB * MB;
    float *Yb = g_Y + (size_t)b * SS * DIM + h * HD;
    __syncthreads();

    // prime the load pipeline
    int base0 = m * HD + l;
    float q0 = Qb[base0], q1 = Qb[base0 + 32];
    float k0 = Kb[base0], k1 = Kb[base0 + 32];
    float v0 = Vb[base0], v1 = Vb[base0 + 32];
    float e  = eb[m];

    for (int n = 0; n < NMB; n++) {
        float cq0 = q0, cq1 = q1, ck0 = k0, ck1 = k1, cv0 = v0, cv1 = v1, ce = e;
        int np = (n + 1 < NMB) ? n + 1 : n;
        int basen = (np * MB + m) * HD + l;
        q0 = Qb[basen]; q1 = Qb[basen + 32];
        k0 = Kb[basen]; k1 = Kb[basen + 32];
        v0 = Vb[basen]; v1 = Vb[basen + 32];
        e  = eb[np * MB + m];

        float bk0[NB], bk1[NB];
        bspline11u(ck0, kn, i1, i2, i3, bk0);
        bspline11u(ck1, kn, i1, i2, i3, bk1);

        float z0 = ck0 / (1.0f + __expf(-ck0));
        float z1 = ck1 / (1.0f + __expf(-ck1));
#pragma unroll
        for (int j = 0; j < NB; j++) {
            z0 = fmaf(bk0[j], Ws[j * HD + l], z0);
            z1 = fmaf(bk1[j], Ws[j * HD + l + 32], z1);
        }
        float s1 = z0 + z1, s2 = fmaf(z0, z0, z1 * z1);
        wsum2(s1, s2);
        float mu = s1 * (1.f / 64.f);
        float var = s2 * (1.f / 64.f) - mu * mu;
        float rstd = rsqrtf(var + EPSV);
        float xh0 = (z0 - mu) * rstd, xh1 = (z1 - mu) * rstd;
        float gh0 = (fmaf(g0, xh0, be0) - (cv0 - ck0)) * g0;
        float gh1 = (fmaf(g1, xh1, be1) - (cv1 - ck1)) * g1;
        s1 = gh0 + gh1;
        s2 = fmaf(gh0, xh0, gh1 * xh1);
        wsum2(s1, s2);
        float mg = s1 * (1.f / 64.f), mgx = s2 * (1.f / 64.f);
        float gz0 = (gh0 - mg - xh0 * mgx) * rstd;
        float gz1 = (gh1 - mg - xh1 * mgx) * rstd;

        float eg0 = ce * gz0, eg1 = ce * gz1;
#pragma unroll
        for (int j = 0; j < NB; j++) {
            tokbuf[(m * NB + j) * HD + l]      = eg0 * bk0[j];
            tokbuf[(m * NB + j) * HD + l + 32] = eg1 * bk1[j];
        }
        __syncthreads();

        for (int idx = tid; idx < NB * HD; idx += 512) {
            float acc = 0.f;
#pragma unroll
            for (int mm = 0; mm < MB; mm++) {
                acc += tokbuf[mm * (NB * HD) + idx];
                tokbuf[mm * (NB * HD) + idx] = acc;
            }
        }
        __syncthreads();

        float bq0[NB], bq1[NB];
        bspline11u(cq0, kn, i1, i2, i3, bq0);
        bspline11u(cq1, kn, i1, i2, i3, bq1);
        float zq0 = cq0 / (1.0f + __expf(-cq0));
        float zq1 = cq1 / (1.0f + __expf(-cq1));
#pragma unroll
        for (int j = 0; j < NB; j++) {
            zq0 = fmaf(bq0[j], Ws[j * HD + l] - tokbuf[(m * NB + j) * HD + l], zq0);
            zq1 = fmaf(bq1[j], Ws[j * HD + l + 32] - tokbuf[(m * NB + j) * HD + l + 32], zq1);
        }
        s1 = zq0 + zq1;
        s2 = fmaf(zq0, zq0, zq1 * zq1);
        wsum2(s1, s2);
        mu = s1 * (1.f / 64.f);
        var = s2 * (1.f / 64.f) - mu * mu;
        rstd = rsqrtf(var + EPSV);
        float y0 = cq0 + fmaf(g0, (zq0 - mu) * rstd, be0);
        float y1 = cq1 + fmaf(g1, (zq1 - mu) * rstd, be1);

        size_t yo = (size_t)(n * MB + m) * DIM;
        Yb[yo + l] = y0;
        Yb[yo + l + 32] = y1;

        __syncthreads();
        for (int idx = tid; idx < NB * HD; idx += 512)
            Ws[idx] -= tokbuf[15 * (NB * HD) + idx];
        __syncthreads();
    }
}

// ---------------------------------------------------------------------------
// Final layernorm over DIM, writes tf32-split g_nh/g_nl
// ---------------------------------------------------------------------------
__global__ __launch_bounds__(256) void ln_kernel(const float *__restrict__ pw,
                                                 const float *__restrict__ pb) {
    int row = blockIdx.x;
    int tid = threadIdx.x;
    float4 v = *((const float4 *)(g_Y + (size_t)row * 1024) + tid);
    float s1 = v.x + v.y + v.z + v.w;
    float s2 = v.x * v.x + v.y * v.y + v.z * v.z + v.w * v.w;
    wsum2(s1, s2);
    __shared__ float sa[8], sb[8];
    int w = tid >> 5, l = tid & 31;
    if (l == 0) { sa[w] = s1; sb[w] = s2; }
    __syncthreads();
    s1 = 0.f; s2 = 0.f;
#pragma unroll
    for (int i = 0; i < 8; i++) { s1 += sa[i]; s2 += sb[i]; }
    float mu = s1 * (1.f / 1024.f);
    float var = s2 * (1.f / 1024.f) - mu * mu;
    float rstd = rsqrtf(var + EPSV);
    float4 pwv = *((const float4 *)pw + tid);
    float4 pbv = *((const float4 *)pb + tid);
    float4 o;
    o.x = (v.x - mu) * rstd * pwv.x + pbv.x;
    o.y = (v.y - mu) * rstd * pwv.y + pbv.y;
    o.z = (v.z - mu) * rstd * pwv.z + pbv.z;
    o.w = (v.w - mu) * rstd * pwv.w + pbv.w;
    uint4 hh, ll;
    split_tf32(o.x, hh.x, ll.x);
    split_tf32(o.y, hh.y, ll.y);
    split_tf32(o.z, hh.z, ll.z);
    split_tf32(o.w, hh.w, ll.w);
    *((uint4 *)(g_nh + (size_t)row * 1024) + tid) = hh;
    *((uint4 *)(g_nl + (size_t)row * 1024) + tid) = ll;
}

// ---------------------------------------------------------------------------
// Launch
// ---------------------------------------------------------------------------
extern "C" void kernel_launch(void *const *d_in, const int *in_sizes, int n_in,
                              void *d_out, int out_size) {
    const float *x     = (const float *)d_in[0];
    const float *posf  = (const float *)d_in[1];
    const float *Wq    = (const float *)d_in[2];
    const float *Wk    = (const float *)d_in[3];
    const float *Wv    = (const float *)d_in[4];
    const float *Wo    = (const float *)d_in[5];
    const float *lrW   = (const float *)d_in[6];
    const float *lrb   = (const float *)d_in[7];
    const float *gsc   = (const float *)d_in[8];
    const float *tgam  = (const float *)d_in[9];
    const float *tbet  = (const float *)d_in[10];
    const float *postw = (const float *)d_in[11];
    const float *postb = (const float *)d_in[12];
    const float *coeff = (const float *)d_in[13];
    const float *knots = (const float *)d_in[14];
    float *out = (float *)d_out;

    rope_tab_kernel<<<(SS * (HD / 2) + 1023) / 1024, 1024>>>(posf);

    // tf32 splits: x and the four weight matrices
    uint32_t *xh, *xl, *wh, *wl;
    cudaGetSymbolAddress((void **)&xh, g_xh);
    cudaGetSymbolAddress((void **)&xl, g_xl);
    cudaGetSymbolAddress((void **)&wh, g_wh);
    cudaGetSymbolAddress((void **)&wl, g_wl);
    int n4x = BB * SS * DIM / 4;
    int n4w = DIM * DIM / 4;
    split_kernel<<<(n4x + 255) / 256, 256>>>((const float4 *)x, (uint4 *)xh,
                                             (uint4 *)xl, n4x);
    const float *Wmats[4] = {Wq, Wk, Wv, Wo};
    for (int i = 0; i < 4; i++)
        split_kernel<<<(n4w + 255) / 256, 256>>>(
            (const float4 *)Wmats[i],
            (uint4 *)(wh + (size_t)i * DIM * DIM),
            (uint4 *)(wl + (size_t)i * DIM * DIM), n4w);

    tc_qkv_kernel<<<dim3(DIM / 128, BB * SS / 128, 3), 256>>>();
    eta_kernel<<<BB * SS, 128>>>(x, lrW, lrb, gsc);
    scan_kernel<<<BB * HH, 512>>>(tgam, tbet, knots, coeff);
    ln_kernel<<<BB * SS, 256>>>(postw, postb);
    tc_out_kernel<<<dim3(DIM / 128, BB * SS / 128, 1), 256>>>(out);
}

// round 5
// speedup vs baseline: 2.9977x; 1.8217x over previous
#include <cuda_runtime.h>
#include <cstdint>

// ---------------------------------------------------------------------------
// Problem constants
// ---------------------------------------------------------------------------
#define BB   4
#define SS   2048
#define DIM  1024
#define HH   16
#define HD   64
#define MB   16
#define NMB  128           // S / MB
#define NB   11            // CP + DEG
#define NKNOTS 15
#define EPSV 1e-6f

// ---------------------------------------------------------------------------
// Device scratch (no cudaMalloc allowed)
// ---------------------------------------------------------------------------
__device__ float g_Q[(size_t)BB * HH * SS * HD];   // (b,h,s,d)
__device__ float g_K[(size_t)BB * HH * SS * HD];
__device__ float g_V[(size_t)BB * HH * SS * HD];
__device__ float g_Y[(size_t)BB * SS * DIM];       // (b,s,dim) -> LN in place
__device__ float g_eta[(size_t)BB * HH * NMB * MB];
__device__ float g_cos[SS * (HD / 2)];
__device__ float g_sin[SS * (HD / 2)];

// ---------------------------------------------------------------------------
// Helpers
// ---------------------------------------------------------------------------
__device__ __forceinline__ void wsum2(float &a, float &b) {
#pragma unroll
    for (int o = 16; o > 0; o >>= 1) {
        a += __shfl_xor_sync(0xffffffffu, a, o);
        b += __shfl_xor_sync(0xffffffffu, b, o);
    }
}

__device__ __forceinline__ uint32_t f2tf32(float x) {
    uint32_t r;
    asm("cvt.rna.tf32.f32 %0, %1;" : "=r"(r) : "f"(x));
    return r;
}

__device__ __forceinline__ uint4 cvt4(uint4 v) {
    uint4 r;
    r.x = f2tf32(__uint_as_float(v.x));
    r.y = f2tf32(__uint_as_float(v.y));
    r.z = f2tf32(__uint_as_float(v.z));
    r.w = f2tf32(__uint_as_float(v.w));
    return r;
}

__device__ __forceinline__ void mma_tf32(float *d, const uint32_t *a,
                                         const uint32_t *b) {
    asm volatile(
        "mma.sync.aligned.m16n8k8.row.col.f32.tf32.tf32.f32 "
        "{%0,%1,%2,%3}, {%4,%5,%6,%7}, {%8,%9}, {%0,%1,%2,%3};\n"
        : "+f"(d[0]), "+f"(d[1]), "+f"(d[2]), "+f"(d[3])
        : "r"(a[0]), "r"(a[1]), "r"(a[2]), "r"(a[3]), "r"(b[0]), "r"(b[1]));
}

// Uniform-knot cubic B-spline: 11 basis values, zero divisions in the loop.
__device__ __forceinline__ void bspline11u(float x, const float *__restrict__ kn,
                                           float i1, float i2, float i3,
                                           float *__restrict__ out) {
    float b[14];
#pragma unroll
    for (int j = 0; j < 14; j++)
        b[j] = (x >= kn[j] && x < kn[j + 1]) ? 1.0f : 0.0f;
#pragma unroll
    for (int j = 0; j < 13; j++)
        b[j] = ((x - kn[j]) * b[j] + (kn[j + 2] - x) * b[j + 1]) * i1;
#pragma unroll
    for (int j = 0; j < 12; j++)
        b[j] = ((x - kn[j]) * b[j] + (kn[j + 3] - x) * b[j + 1]) * i2;
#pragma unroll
    for (int j = 0; j < 11; j++)
        b[j] = ((x - kn[j]) * b[j] + (kn[j + 4] - x) * b[j + 1]) * i3;
#pragma unroll
    for (int j = 0; j < NB; j++) out[j] = b[j];
}

// ---------------------------------------------------------------------------
// RoPE table: double-precision cos/sin of the fp32 angles
// ---------------------------------------------------------------------------
__global__ void rope_tab_kernel(const float *__restrict__ posf) {
    int i = blockIdx.x * blockDim.x + threadIdx.x;
    if (i < SS * (HD / 2)) {
        double a = (double)posf[i];
        g_cos[i] = (float)cos(a);
        g_sin[i] = (float)sin(a);
    }
}

// ---------------------------------------------------------------------------
// 1xTF32 tensor-core GEMM core (rna-rounded operands).
// C(128x128) = A(128xK) * W(128xK)^T ; 256 thr = 8 warps 2(M)x4(N)
// ---------------------------------------------------------------------------
#define SPITCH 20   // smem row pitch (uint32) — 16B-aligned stores, conflict-free

__device__ __forceinline__ void tc_gemm_core(
    const float *__restrict__ A, const float *__restrict__ B,
    uint32_t *As, uint32_t *Bs,
    float (&acc)[4][4][4], int rowBase, int colBase) {
    int tid = threadIdx.x;
    int lane = tid & 31, wid = tid >> 5;
    int wm = wid >> 2, wn = wid & 3;
    int r0 = tid >> 2, c4 = (tid & 3) << 2;

    const uint4 *pA = (const uint4 *)(A + (size_t)(rowBase + r0) * 1024 + c4);
    const uint4 *pB = (const uint4 *)(B + (size_t)(colBase + r0) * 1024 + c4);
    const int rstep = 64 * 1024 / 4;   // +64 rows, in uint4 units

    uint4 va0 = pA[0], va1 = pA[rstep];
    uint4 vb0 = pB[0], vb1 = pB[rstep];

    for (int k0 = 0; k0 < 1024; k0 += 16) {
        __syncthreads();
        *(uint4 *)&As[r0 * SPITCH + c4] = cvt4(va0);
        *(uint4 *)&As[(r0 + 64) * SPITCH + c4] = cvt4(va1);
        *(uint4 *)&Bs[r0 * SPITCH + c4] = cvt4(vb0);
        *(uint4 *)&Bs[(r0 + 64) * SPITCH + c4] = cvt4(vb1);
        __syncthreads();
        if (k0 + 16 < 1024) {
            int ko = (k0 + 16) >> 2;
            va0 = pA[ko]; va1 = pA[ko + rstep];
            vb0 = pB[ko]; vb1 = pB[ko + rstep];
        }
#pragma unroll
        for (int ks = 0; ks < 2; ks++) {
            int kb = ks * 8 + (lane & 3);
            uint32_t ah[4][4], bh[4][2];
#pragma unroll
            for (int mt = 0; mt < 4; mt++) {
                int row = wm * 64 + mt * 16 + (lane >> 2);
                ah[mt][0] = As[row * SPITCH + kb];
                ah[mt][1] = As[(row + 8) * SPITCH + kb];
                ah[mt][2] = As[row * SPITCH + kb + 4];
                ah[mt][3] = As[(row + 8) * SPITCH + kb + 4];
            }
#pragma unroll
            for (int nt = 0; nt < 4; nt++) {
                int col = wn * 32 + nt * 8 + (lane >> 2);
                bh[nt][0] = Bs[col * SPITCH + kb];
                bh[nt][1] = Bs[col * SPITCH + kb + 4];
            }
#pragma unroll
            for (int mt = 0; mt < 4; mt++)
#pragma unroll
                for (int nt = 0; nt < 4; nt++)
                    mma_tf32(acc[mt][nt], ah[mt], bh[nt]);
        }
    }
}

// QKV projection + RoPE, scattering into (b,h,s,d) layout. blockIdx.z in {0,1,2}
__global__ __launch_bounds__(256) void tc_qkv_kernel(
    const float *__restrict__ x, const float *__restrict__ Wq,
    const float *__restrict__ Wk, const float *__restrict__ Wv) {
    __shared__ uint32_t As[128 * SPITCH], Bs[128 * SPITCH];
    const float *W = (blockIdx.z == 0) ? Wq : (blockIdx.z == 1) ? Wk : Wv;
    float *O = (blockIdx.z == 0) ? g_Q : (blockIdx.z == 1) ? g_K : g_V;

    float acc[4][4][4];
#pragma unroll
    for (int a = 0; a < 4; a++)
#pragma unroll
        for (int b = 0; b < 4; b++)
#pragma unroll
            for (int c = 0; c < 4; c++) acc[a][b][c] = 0.f;

    int rowBase = blockIdx.y * 128, colBase = blockIdx.x * 128;
    tc_gemm_core(x, W, As, Bs, acc, rowBase, colBase);

    int lane = threadIdx.x & 31, wid = threadIdx.x >> 5;
    int wm = wid >> 2, wn = wid & 3;
#pragma unroll
    for (int mt = 0; mt < 4; mt++) {
        int r = rowBase + wm * 64 + mt * 16 + (lane >> 2);
#pragma unroll
        for (int half = 0; half < 2; half++) {
            int ri = r + half * 8;
            int b = ri >> 11;  // S = 2048
            int s = ri & 2047;
#pragma unroll
            for (int nt = 0; nt < 4; nt++) {
                int c = colBase + wn * 32 + nt * 8 + 2 * (lane & 3);
                int h = c >> 6;
                int dd = c & 63;
                int jj = dd >> 1;
                float cs = g_cos[s * 32 + jj];
                float sn = g_sin[s * 32 + jj];
                float t1 = acc[mt][nt][2 * half];
                float t2 = acc[mt][nt][2 * half + 1];
                size_t o = (((size_t)(b * HH + h) * SS) + s) * HD + dd;
                O[o]     = t1 * cs - t2 * sn;
                O[o + 1] = t1 * sn + t2 * cs;
            }
        }
    }
}

// Final projection: d_out = Y_normalized @ Wo^T
__global__ __launch_bounds__(256) void tc_out_kernel(const float *__restrict__ Wo,
                                                     float *__restrict__ out) {
    __shared__ uint32_t As[128 * SPITCH], Bs[128 * SPITCH];
    float acc[4][4][4];
#pragma unroll
    for (int a = 0; a < 4; a++)
#pragma unroll
        for (int b = 0; b < 4; b++)
#pragma unroll
            for (int c = 0; c < 4; c++) acc[a][b][c] = 0.f;

    int rowBase = blockIdx.y * 128, colBase = blockIdx.x * 128;
    tc_gemm_core(g_Y, Wo, As, Bs, acc, rowBase, colBase);

    int lane = threadIdx.x & 31, wid = threadIdx.x >> 5;
    int wm = wid >> 2, wn = wid & 3;
#pragma unroll
    for (int mt = 0; mt < 4; mt++) {
        int r = rowBase + wm * 64 + mt * 16 + (lane >> 2);
#pragma unroll
        for (int half = 0; half < 2; half++) {
            size_t ri = r + half * 8;
#pragma unroll
            for (int nt = 0; nt < 4; nt++) {
                int c = colBase + wn * 32 + nt * 8 + 2 * (lane & 3);
                float2 v = make_float2(acc[mt][nt][2 * half],
                                       acc[mt][nt][2 * half + 1]);
                *(float2 *)(out + ri * 1024 + c) = v;
            }
        }
    }
}

// ---------------------------------------------------------------------------
// eta = sigmoid(x . lr_W[h] + lr_b[h]) / HD * gs[m]
// ---------------------------------------------------------------------------
__global__ __launch_bounds__(128) void eta_kernel(
    const float *__restrict__ x, const float *__restrict__ lrW,
    const float *__restrict__ lrb, const float *__restrict__ gsc) {
    int row = blockIdx.x;  // b*2048 + s
    __shared__ float xs[1024];
    const float4 *xp = (const float4 *)(x + (size_t)row * 1024);
    float4 *xsp = (float4 *)xs;
    xsp[threadIdx.x] = xp[threadIdx.x];
    xsp[threadIdx.x + 128] = xp[threadIdx.x + 128];
    __syncthreads();

    int w = threadIdx.x >> 5, l = threadIdx.x & 31;
    int b = row >> 11, s = row & 2047;
    int n = s >> 4, m = s & 15;
    float gs = fmaxf(1.0f / (float)(m + 1) + gsc[m], 0.0f);

#pragma unroll
    for (int hh = 0; hh < 4; hh++) {
        int h = w * 4 + hh;
        const float *wp = lrW + (size_t)h * 1024;
        float sum = 0.f;
        for (int k = l; k < 1024; k += 32) sum = fmaf(xs[k], wp[k], sum);
#pragma unroll
        for (int o = 16; o > 0; o >>= 1) sum += __shfl_xor_sync(0xffffffffu, sum, o);
        if (l == 0) {
            float lr = 1.0f / (1.0f + __expf(-(sum + lrb[h]))) * (1.0f / 64.0f);
            g_eta[(((size_t)b * HH + h) * NMB + n) * MB + m] = lr * gs;
        }
    }
}

// ---------------------------------------------------------------------------
// Sequential TTT scan: one CTA per (b,h), 512 threads (warp=m, lane covers d,d+32)
// ---------------------------------------------------------------------------
__global__ __launch_bounds__(512) void scan_kernel(
    const float *__restrict__ gamma, const float *__restrict__ beta,
    const float *__restrict__ knots, const float *__restrict__ coeff) {
    __shared__ float Ws[NB * HD];           // 2816 B
    __shared__ float tokbuf[MB * NB * HD];  // 45056 B

    int bh = blockIdx.x;
    int b = bh >> 4, h = bh & 15;
    int tid = threadIdx.x, m = tid >> 5, l = tid & 31;

    float kn[NKNOTS];
#pragma unroll
    for (int j = 0; j < NKNOTS; j++) kn[j] = knots[j];
    float hstep = (kn[NKNOTS - 1] - kn[0]) * (1.0f / (float)(NKNOTS - 1));
    float i1 = 1.0f / hstep;
    float i2 = 0.5f / hstep;
    float i3 = 1.0f / (3.0f * hstep);

    float g0 = gamma[h * HD + l], g1 = gamma[h * HD + l + 32];
    float be0 = beta[h * HD + l], be1 = beta[h * HD + l + 32];

    for (int idx = tid; idx < NB * HD; idx += 512)
        Ws[idx] = coeff[(size_t)h * NB * HD + idx];

    const float *Qb = g_Q + (size_t)bh * SS * HD;
    const float *Kb = g_K + (size_t)bh * SS * HD;
    const float *Vb = g_V + (size_t)bh * SS * HD;
    const float *eb = g_eta + (size_t)bh * NMB * MB;
    float *Yb = g_Y + (size_t)b * SS * DIM + h * HD;
    __syncthreads();

    int base0 = m * HD + l;
    float q0 = Qb[base0], q1 = Qb[base0 + 32];
    float k0 = Kb[base0], k1 = Kb[base0 + 32];
    float v0 = Vb[base0], v1 = Vb[base0 + 32];
    float e  = eb[m];

    for (int n = 0; n < NMB; n++) {
        float cq0 = q0, cq1 = q1, ck0 = k0, ck1 = k1, cv0 = v0, cv1 = v1, ce = e;
        int np = (n + 1 < NMB) ? n + 1 : n;
        int basen = (np * MB + m) * HD + l;
        q0 = Qb[basen]; q1 = Qb[basen + 32];
        k0 = Kb[basen]; k1 = Kb[basen + 32];
        v0 = Vb[basen]; v1 = Vb[basen + 32];
        e  = eb[np * MB + m];

        float bk0[NB], bk1[NB];
        bspline11u(ck0, kn, i1, i2, i3, bk0);
        bspline11u(ck1, kn, i1, i2, i3, bk1);

        float z0 = ck0 / (1.0f + __expf(-ck0));
        float z1 = ck1 / (1.0f + __expf(-ck1));
#pragma unroll
        for (int j = 0; j < NB; j++) {
            z0 = fmaf(bk0[j], Ws[j * HD + l], z0);
            z1 = fmaf(bk1[j], Ws[j * HD + l + 32], z1);
        }
        float s1 = z0 + z1, s2 = fmaf(z0, z0, z1 * z1);
        wsum2(s1, s2);
        float mu = s1 * (1.f / 64.f);
        float var = s2 * (1.f / 64.f) - mu * mu;
        float rstd = rsqrtf(var + EPSV);
        float xh0 = (z0 - mu) * rstd, xh1 = (z1 - mu) * rstd;
        float gh0 = (fmaf(g0, xh0, be0) - (cv0 - ck0)) * g0;
        float gh1 = (fmaf(g1, xh1, be1) - (cv1 - ck1)) * g1;
        s1 = gh0 + gh1;
        s2 = fmaf(gh0, xh0, gh1 * xh1);
        wsum2(s1, s2);
        float mg = s1 * (1.f / 64.f), mgx = s2 * (1.f / 64.f);
        float gz0 = (gh0 - mg - xh0 * mgx) * rstd;
        float gz1 = (gh1 - mg - xh1 * mgx) * rstd;

        float eg0 = ce * gz0, eg1 = ce * gz1;
#pragma unroll
        for (int j = 0; j < NB; j++) {
            tokbuf[(m * NB + j) * HD + l]      = eg0 * bk0[j];
            tokbuf[(m * NB + j) * HD + l + 32] = eg1 * bk1[j];
        }
        __syncthreads();

        for (int idx = tid; idx < NB * HD; idx += 512) {
            float acc = 0.f;
#pragma unroll
            for (int mm = 0; mm < MB; mm++) {
                acc += tokbuf[mm * (NB * HD) + idx];
                tokbuf[mm * (NB * HD) + idx] = acc;
            }
        }
        __syncthreads();

        float bq0[NB], bq1[NB];
        bspline11u(cq0, kn, i1, i2, i3, bq0);
        bspline11u(cq1, kn, i1, i2, i3, bq1);
        float zq0 = cq0 / (1.0f + __expf(-cq0));
        float zq1 = cq1 / (1.0f + __expf(-cq1));
#pragma unroll
        for (int j = 0; j < NB; j++) {
            zq0 = fmaf(bq0[j], Ws[j * HD + l] - tokbuf[(m * NB + j) * HD + l], zq0);
            zq1 = fmaf(bq1[j], Ws[j * HD + l + 32] - tokbuf[(m * NB + j) * HD + l + 32], zq1);
        }
        s1 = zq0 + zq1;
        s2 = fmaf(zq0, zq0, zq1 * zq1);
        wsum2(s1, s2);
        mu = s1 * (1.f / 64.f);
        var = s2 * (1.f / 64.f) - mu * mu;
        rstd = rsqrtf(var + EPSV);
        float y0 = cq0 + fmaf(g0, (zq0 - mu) * rstd, be0);
        float y1 = cq1 + fmaf(g1, (zq1 - mu) * rstd, be1);

        size_t yo = (size_t)(n * MB + m) * DIM;
        Yb[yo + l] = y0;
        Yb[yo + l + 32] = y1;

        __syncthreads();
        for (int idx = tid; idx < NB * HD; idx += 512)
            Ws[idx] -= tokbuf[15 * (NB * HD) + idx];
        __syncthreads();
    }
}

// ---------------------------------------------------------------------------
// Final layernorm over DIM, in place on g_Y
// ---------------------------------------------------------------------------
__global__ __launch_bounds__(256) void ln_kernel(const float *__restrict__ pw,
                                                 const float *__restrict__ pb) {
    int row = blockIdx.x;
    int tid = threadIdx.x;
    float4 v = *((const float4 *)(g_Y + (size_t)row * 1024) + tid);
    float s1 = v.x + v.y + v.z + v.w;
    float s2 = v.x * v.x + v.y * v.y + v.z * v.z + v.w * v.w;
    wsum2(s1, s2);
    __shared__ float sa[8], sb[8];
    int w = tid >> 5, l = tid & 31;
    if (l == 0) { sa[w] = s1; sb[w] = s2; }
    __syncthreads();
    s1 = 0.f; s2 = 0.f;
#pragma unroll
    for (int i = 0; i < 8; i++) { s1 += sa[i]; s2 += sb[i]; }
    float mu = s1 * (1.f / 1024.f);
    float var = s2 * (1.f / 1024.f) - mu * mu;
    float rstd = rsqrtf(var + EPSV);
    float4 pwv = *((const float4 *)pw + tid);
    float4 pbv = *((const float4 *)pb + tid);
    float4 o;
    o.x = (v.x - mu) * rstd * pwv.x + pbv.x;
    o.y = (v.y - mu) * rstd * pwv.y + pbv.y;
    o.z = (v.z - mu) * rstd * pwv.z + pbv.z;
    o.w = (v.w - mu) * rstd * pwv.w + pbv.w;
    *((float4 *)(g_Y + (size_t)row * 1024) + tid) = o;
}

// ---------------------------------------------------------------------------
// Launch
// ---------------------------------------------------------------------------
extern "C" void kernel_launch(void *const *d_in, const int *in_sizes, int n_in,
                              void *d_out, int out_size) {
    const float *x     = (const float *)d_in[0];
    const float *posf  = (const float *)d_in[1];
    const float *Wq    = (const float *)d_in[2];
    const float *Wk    = (const float *)d_in[3];
    const float *Wv    = (const float *)d_in[4];
    const float *Wo    = (const float *)d_in[5];
    const float *lrW   = (const float *)d_in[6];
    const float *lrb   = (const float *)d_in[7];
    const float *gsc   = (const float *)d_in[8];
    const float *tgam  = (const float *)d_in[9];
    const float *tbet  = (const float *)d_in[10];
    const float *postw = (const float *)d_in[11];
    const float *postb = (const float *)d_in[12];
    const float *coeff = (const float *)d_in[13];
    const float *knots = (const float *)d_in[14];
    float *out = (float *)d_out;

    rope_tab_kernel<<<(SS * (HD / 2) + 1023) / 1024, 1024>>>(posf);
    tc_qkv_kernel<<<dim3(DIM / 128, BB * SS / 128, 3), 256>>>(x, Wq, Wk, Wv);
    eta_kernel<<<BB * SS, 128>>>(x, lrW, lrb, gsc);
    scan_kernel<<<BB * HH, 512>>>(tgam, tbet, knots, coeff);
    ln_kernel<<<BB * SS, 256>>>(postw, postb);
    tc_out_kernel<<<dim3(DIM / 128, BB * SS / 128, 1), 256>>>(Wo, out);
}

// round 7
// speedup vs baseline: 3.6886x; 1.2305x over previous
#include <cuda_runtime.h>
#include <cstdint>

// ---------------------------------------------------------------------------
// Problem constants
// ---------------------------------------------------------------------------
#define BB   4
#define SS   2048
#define DIM  1024
#define HH   16
#define HD   64
#define MB   16
#define NMB  128           // S / MB
#define NB   11            // CP + DEG
#define NKNOTS 15
#define EPSV 1e-6f
#define TPITCH 768         // 12 * 64 floats per m-block in tokbuf

// ---------------------------------------------------------------------------
// Device scratch (no cudaMalloc allowed)
// ---------------------------------------------------------------------------
__device__ float g_Q[(size_t)BB * HH * SS * HD];   // (b,h,s,d)
__device__ float g_K[(size_t)BB * HH * SS * HD];
__device__ float g_V[(size_t)BB * HH * SS * HD];
__device__ float g_Y[(size_t)BB * SS * DIM];       // (b,s,dim) -> LN in place
__device__ float g_eta[(size_t)BB * HH * NMB * MB];
__device__ float g_cos[SS * (HD / 2)];
__device__ float g_sin[SS * (HD / 2)];

// ---------------------------------------------------------------------------
// Helpers
// ---------------------------------------------------------------------------
__device__ __forceinline__ void wsum2(float &a, float &b) {
#pragma unroll
    for (int o = 16; o > 0; o >>= 1) {
        a += __shfl_xor_sync(0xffffffffu, a, o);
        b += __shfl_xor_sync(0xffffffffu, b, o);
    }
}

__device__ __forceinline__ uint32_t f2tf32(float x) {
    uint32_t r;
    asm("cvt.rna.tf32.f32 %0, %1;" : "=r"(r) : "f"(x));
    return r;
}

__device__ __forceinline__ uint4 cvt4(uint4 v) {
    uint4 r;
    r.x = f2tf32(__uint_as_float(v.x));
    r.y = f2tf32(__uint_as_float(v.y));
    r.z = f2tf32(__uint_as_float(v.z));
    r.w = f2tf32(__uint_as_float(v.w));
    return r;
}

__device__ __forceinline__ void mma_tf32(float *d, const uint32_t *a,
                                         const uint32_t *b) {
    asm volatile(
        "mma.sync.aligned.m16n8k8.row.col.f32.tf32.tf32.f32 "
        "{%0,%1,%2,%3}, {%4,%5,%6,%7}, {%8,%9}, {%0,%1,%2,%3};\n"
        : "+f"(d[0]), "+f"(d[1]), "+f"(d[2]), "+f"(d[3])
        : "r"(a[0]), "r"(a[1]), "r"(a[2]), "r"(a[3]), "r"(b[0]), "r"(b[1]));
}

// Sparse uniform-knot cubic B-spline: at most 4 nonzero basis values.
// Returns jbase = idx-3 and weights w[0..3] for j = jbase..jbase+3,
// fully masked (0 if x outside knot range or j outside [0, NB-1]).
__device__ __forceinline__ void bspline4(float x, float kn0, float inv_h,
                                         int &jbase, float (&w)[4]) {
    float u = (x - kn0) * inv_h;
    float fi = floorf(u);
    float t = u - fi;
    int idx = (int)fi;
    bool valid = (u >= 0.0f) && (u < 14.0f);
    float t2 = t * t, t3 = t2 * t;
    float omt = 1.0f - t;
    const float s = 1.0f / 6.0f;
    jbase = idx - 3;
    float w0 = omt * omt * omt * s;                               // j=idx-3
    float w1 = fmaf(3.f, t3, fmaf(-6.f, t2, 4.f)) * s;            // j=idx-2
    float w2 = fmaf(-3.f, t3, fmaf(3.f, t2, fmaf(3.f, t, 1.f))) * s; // j=idx-1
    float w3 = t3 * s;                                            // j=idx
    w[0] = (valid && jbase >= 0 && jbase <= 10) ? w0 : 0.f;
    w[1] = (valid && jbase + 1 >= 0 && jbase + 1 <= 10) ? w1 : 0.f;
    w[2] = (valid && jbase + 2 >= 0 && jbase + 2 <= 10) ? w2 : 0.f;
    w[3] = (valid && jbase + 3 <= 10) ? w3 : 0.f;
}

__device__ __forceinline__ int clampj(int j) {
    return j < 0 ? 0 : (j > 10 ? 10 : j);
}

// ---------------------------------------------------------------------------
// RoPE table: double-precision cos/sin of the fp32 angles
// ---------------------------------------------------------------------------
__global__ void rope_tab_kernel(const float *__restrict__ posf) {
    int i = blockIdx.x * blockDim.x + threadIdx.x;
    if (i < SS * (HD / 2)) {
        double a = (double)posf[i];
        g_cos[i] = (float)cos(a);
        g_sin[i] = (float)sin(a);
    }
}

// ---------------------------------------------------------------------------
// 1xTF32 tensor-core GEMM core (rna-rounded operands).
// C(128x128) = A(128xK) * W(128xK)^T ; 256 thr = 8 warps 2(M)x4(N)
// ---------------------------------------------------------------------------
#define SPITCH 20   // smem row pitch (uint32) — 16B-aligned stores, conflict-free

__device__ __forceinline__ void tc_gemm_core(
    const float *__restrict__ A, const float *__restrict__ B,
    uint32_t *As, uint32_t *Bs,
    float (&acc)[4][4][4], int rowBase, int colBase) {
    int tid = threadIdx.x;
    int lane = tid & 31, wid = tid >> 5;
    int wm = wid >> 2, wn = wid & 3;
    int r0 = tid >> 2, c4 = (tid & 3) << 2;

    const uint4 *pA = (const uint4 *)(A + (size_t)(rowBase + r0) * 1024 + c4);
    const uint4 *pB = (const uint4 *)(B + (size_t)(colBase + r0) * 1024 + c4);
    const int rstep = 64 * 1024 / 4;   // +64 rows, in uint4 units

    uint4 va0 = pA[0], va1 = pA[rstep];
    uint4 vb0 = pB[0], vb1 = pB[rstep];

    for (int k0 = 0; k0 < 1024; k0 += 16) {
        __syncthreads();
        *(uint4 *)&As[r0 * SPITCH + c4] = cvt4(va0);
        *(uint4 *)&As[(r0 + 64) * SPITCH + c4] = cvt4(va1);
        *(uint4 *)&Bs[r0 * SPITCH + c4] = cvt4(vb0);
        *(uint4 *)&Bs[(r0 + 64) * SPITCH + c4] = cvt4(vb1);
        __syncthreads();
        if (k0 + 16 < 1024) {
            int ko = (k0 + 16) >> 2;
            va0 = pA[ko]; va1 = pA[ko + rstep];
            vb0 = pB[ko]; vb1 = pB[ko + rstep];
        }
#pragma unroll
        for (int ks = 0; ks < 2; ks++) {
            int kb = ks * 8 + (lane & 3);
            uint32_t ah[4][4], bh[4][2];
#pragma unroll
            for (int mt = 0; mt < 4; mt++) {
                int row = wm * 64 + mt * 16 + (lane >> 2);
                ah[mt][0] = As[row * SPITCH + kb];
                ah[mt][1] = As[(row + 8) * SPITCH + kb];
                ah[mt][2] = As[row * SPITCH + kb + 4];
                ah[mt][3] = As[(row + 8) * SPITCH + kb + 4];
            }
#pragma unroll
            for (int nt = 0; nt < 4; nt++) {
                int col = wn * 32 + nt * 8 + (lane >> 2);
                bh[nt][0] = Bs[col * SPITCH + kb];
                bh[nt][1] = Bs[col * SPITCH + kb + 4];
            }
#pragma unroll
            for (int mt = 0; mt < 4; mt++)
#pragma unroll
                for (int nt = 0; nt < 4; nt++)
                    mma_tf32(acc[mt][nt], ah[mt], bh[nt]);
        }
    }
}

// QKV projection + RoPE, scattering into (b,h,s,d) layout. blockIdx.z in {0,1,2}
__global__ __launch_bounds__(256) void tc_qkv_kernel(
    const float *__restrict__ x, const float *__restrict__ Wq,
    const float *__restrict__ Wk, const float *__restrict__ Wv) {
    __shared__ uint32_t As[128 * SPITCH], Bs[128 * SPITCH];
    const float *W = (blockIdx.z == 0) ? Wq : (blockIdx.z == 1) ? Wk : Wv;
    float *O = (blockIdx.z == 0) ? g_Q : (blockIdx.z == 1) ? g_K : g_V;

    float acc[4][4][4];
#pragma unroll
    for (int a = 0; a < 4; a++)
#pragma unroll
        for (int b = 0; b < 4; b++)
#pragma unroll
            for (int c = 0; c < 4; c++) acc[a][b][c] = 0.f;

    int rowBase = blockIdx.y * 128, colBase = blockIdx.x * 128;
    tc_gemm_core(x, W, As, Bs, acc, rowBase, colBase);

    int lane = threadIdx.x & 31, wid = threadIdx.x >> 5;
    int wm = wid >> 2, wn = wid & 3;
#pragma unroll
    for (int mt = 0; mt < 4; mt++) {
        int r = rowBase + wm * 64 + mt * 16 + (lane >> 2);
#pragma unroll
        for (int half = 0; half < 2; half++) {
            int ri = r + half * 8;
            int b = ri >> 11;  // S = 2048
            int s = ri & 2047;
#pragma unroll
            for (int nt = 0; nt < 4; nt++) {
                int c = colBase + wn * 32 + nt * 8 + 2 * (lane & 3);
                int h = c >> 6;
                int dd = c & 63;
                int jj = dd >> 1;
                float cs = g_cos[s * 32 + jj];
                float sn = g_sin[s * 32 + jj];
                float t1 = acc[mt][nt][2 * half];
                float t2 = acc[mt][nt][2 * half + 1];
                size_t o = (((size_t)(b * HH + h) * SS) + s) * HD + dd;
                O[o]     = t1 * cs - t2 * sn;
                O[o + 1] = t1 * sn + t2 * cs;
            }
        }
    }
}

// Final projection: d_out = Y_normalized @ Wo^T
__global__ __launch_bounds__(256) void tc_out_kernel(const float *__restrict__ Wo,
                                                     float *__restrict__ out) {
    __shared__ uint32_t As[128 * SPITCH], Bs[128 * SPITCH];
    float acc[4][4][4];
#pragma unroll
    for (int a = 0; a < 4; a++)
#pragma unroll
        for (int b = 0; b < 4; b++)
#pragma unroll
            for (int c = 0; c < 4; c++) acc[a][b][c] = 0.f;

    int rowBase = blockIdx.y * 128, colBase = blockIdx.x * 128;
    tc_gemm_core(g_Y, Wo, As, Bs, acc, rowBase, colBase);

    int lane = threadIdx.x & 31, wid = threadIdx.x >> 5;
    int wm = wid >> 2, wn = wid & 3;
#pragma unroll
    for (int mt = 0; mt < 4; mt++) {
        int r = rowBase + wm * 64 + mt * 16 + (lane >> 2);
#pragma unroll
        for (int half = 0; half < 2; half++) {
            size_t ri = r + half * 8;
#pragma unroll
            for (int nt = 0; nt < 4; nt++) {
                int c = colBase + wn * 32 + nt * 8 + 2 * (lane & 3);
                float2 v = make_float2(acc[mt][nt][2 * half],
                                       acc[mt][nt][2 * half + 1]);
                *(float2 *)(out + ri * 1024 + c) = v;
            }
        }
    }
}

// ---------------------------------------------------------------------------
// eta = sigmoid(x . lr_W[h] + lr_b[h]) / HD * gs[m]
// ---------------------------------------------------------------------------
__global__ __launch_bounds__(128) void eta_kernel(
    const float *__restrict__ x, const float *__restrict__ lrW,
    const float *__restrict__ lrb, const float *__restrict__ gsc) {
    int row = blockIdx.x;  // b*2048 + s
    __shared__ float xs[1024];
    const float4 *xp = (const float4 *)(x + (size_t)row * 1024);
    float4 *xsp = (float4 *)xs;
    xsp[threadIdx.x] = xp[threadIdx.x];
    xsp[threadIdx.x + 128] = xp[threadIdx.x + 128];
    __syncthreads();

    int w = threadIdx.x >> 5, l = threadIdx.x & 31;
    int b = row >> 11, s = row & 2047;
    int n = s >> 4, m = s & 15;
    float gs = fmaxf(1.0f / (float)(m + 1) + gsc[m], 0.0f);

#pragma unroll
    for (int hh = 0; hh < 4; hh++) {
        int h = w * 4 + hh;
        const float *wp = lrW + (size_t)h * 1024;
        float sum = 0.f;
        for (int k = l; k < 1024; k += 32) sum = fmaf(xs[k], wp[k], sum);
#pragma unroll
        for (int o = 16; o > 0; o >>= 1) sum += __shfl_xor_sync(0xffffffffu, sum, o);
        if (l == 0) {
            float lr = 1.0f / (1.0f + __expf(-(sum + lrb[h]))) * (1.0f / 64.0f);
            g_eta[(((size_t)b * HH + h) * NMB + n) * MB + m] = lr * gs;
        }
    }
}

// ---------------------------------------------------------------------------
// Sequential TTT scan: one CTA per (b,h), 512 threads (warp=m, lane covers d,d+32)
// Sparse 4-term B-spline, vectorized cumsum, ping-pong Ws, 3 barriers/iter.
// ---------------------------------------------------------------------------
__global__ __launch_bounds__(512) void scan_kernel(
    const float *__restrict__ gamma, const float *__restrict__ beta,
    const float *__restrict__ knots, const float *__restrict__ coeff) {
    extern __shared__ float sm[];
    float *tokbuf = sm;                       // [MB][12][HD] = 12288 floats
    float *Wsbuf = sm + MB * TPITCH;          // [2][NB*HD]   = 1408 ea

    int bh = blockIdx.x;
    int b = bh >> 4, h = bh & 15;
    int tid = threadIdx.x, m = tid >> 5, l = tid & 31;

    float kn0 = knots[0];
    float kn14 = knots[NKNOTS - 1];
    float inv_h = 14.0f / (kn14 - kn0);

    float g0 = gamma[h * HD + l], g1 = gamma[h * HD + l + 32];
    float be0 = beta[h * HD + l], be1 = beta[h * HD + l + 32];

    for (int idx = tid; idx < NB * HD; idx += 512)
        Wsbuf[idx] = coeff[(size_t)h * NB * HD + idx];

    const float *Qb = g_Q + (size_t)bh * SS * HD;
    const float *Kb = g_K + (size_t)bh * SS * HD;
    const float *Vb = g_V + (size_t)bh * SS * HD;
    const float *eb = g_eta + (size_t)bh * NMB * MB;
    float *Yb = g_Y + (size_t)b * SS * DIM + h * HD;

    // cumsum / W-update work assignment (176 threads, float4 columns)
    float *cbase = tokbuf + (tid >> 4) * HD + ((tid & 15) << 2);
    float *mb = tokbuf + m * TPITCH;   // this warp's m-block

    int cur = 0;
    __syncthreads();

    int base0 = m * HD + l;
    float q0 = Qb[base0], q1 = Qb[base0 + 32];
    float k0 = Kb[base0], k1 = Kb[base0 + 32];
    float v0 = Vb[base0], v1 = Vb[base0 + 32];
    float e  = eb[m];

    for (int n = 0; n < NMB; n++) {
        float cq0 = q0, cq1 = q1, ck0 = k0, ck1 = k1, cv0 = v0, cv1 = v1, ce = e;
        int np = (n + 1 < NMB) ? n + 1 : n;
        int basen = (np * MB + m) * HD + l;
        q0 = Qb[basen]; q1 = Qb[basen + 32];
        k0 = Kb[basen]; k1 = Kb[basen + 32];
        v0 = Vb[basen]; v1 = Vb[basen + 32];
        e  = eb[np * MB + m];

        const float *Wc = Wsbuf + cur * (NB * HD);
        float *Wn = Wsbuf + (cur ^ 1) * (NB * HD);

        // ---- phase A: K basis, Zk, LN-bwd, token write ----
        int jk0, jk1;
        float wk0[4], wk1[4];
        bspline4(ck0, kn0, inv_h, jk0, wk0);
        bspline4(ck1, kn0, inv_h, jk1, wk1);

        float z0 = __fdividef(ck0, 1.0f + __expf(-ck0));
        float z1 = __fdividef(ck1, 1.0f + __expf(-ck1));
#pragma unroll
        for (int k = 0; k < 4; k++) {
            z0 = fmaf(wk0[k], Wc[clampj(jk0 + k) * HD + l], z0);
            z1 = fmaf(wk1[k], Wc[clampj(jk1 + k) * HD + l + 32], z1);
        }
        float s1 = z0 + z1, s2 = fmaf(z0, z0, z1 * z1);
        wsum2(s1, s2);
        float mu = s1 * (1.f / 64.f);
        float var = s2 * (1.f / 64.f) - mu * mu;
        float rstd = rsqrtf(var + EPSV);
        float xh0 = (z0 - mu) * rstd, xh1 = (z1 - mu) * rstd;
        float gh0 = (fmaf(g0, xh0, be0) - (cv0 - ck0)) * g0;
        float gh1 = (fmaf(g1, xh1, be1) - (cv1 - ck1)) * g1;
        s1 = gh0 + gh1;
        s2 = fmaf(gh0, xh0, gh1 * xh1);
        wsum2(s1, s2);
        float mg = s1 * (1.f / 64.f), mgx = s2 * (1.f / 64.f);
        float eg0 = ce * (gh0 - mg - xh0 * mgx) * rstd;
        float eg1 = ce * (gh1 - mg - xh1 * mgx) * rstd;

        // zero this warp's m-block (12 rows x 64 floats) cooperatively
        float4 z4 = make_float4(0.f, 0.f, 0.f, 0.f);
#pragma unroll
        for (int i = 0; i < 6; i++)
            ((float4 *)mb)[i * 32 + l] = z4;
        __syncwarp();
        // scatter the (at most) 4 nonzero contributions per d
#pragma unroll
        for (int k = 0; k < 4; k++) {
            if (wk0[k] != 0.f) mb[(jk0 + k) * HD + l] = eg0 * wk0[k];
            if (wk1[k] != 0.f) mb[(jk1 + k) * HD + l + 32] = eg1 * wk1[k];
        }
        __syncthreads();  // A -> B

        // ---- phase B: inclusive cumsum over m (float4 columns) ----
        if (tid < 176) {
            float4 acc = make_float4(0.f, 0.f, 0.f, 0.f);
            float *p = cbase;
#pragma unroll
            for (int mm = 0; mm < MB; mm++) {
                float4 v = *(float4 *)p;
                acc.x += v.x; acc.y += v.y; acc.z += v.z; acc.w += v.w;
                *(float4 *)p = acc;
                p += TPITCH;
            }
        }
        __syncthreads();  // B -> C

        // ---- phase C: Q basis, Zq, LN-fwd, Y, W update ----
        int jq0, jq1;
        float wq0[4], wq1[4];
        bspline4(cq0, kn0, inv_h, jq0, wq0);
        bspline4(cq1, kn0, inv_h, jq1, wq1);
        float zq0 = __fdividef(cq0, 1.0f + __expf(-cq0));
        float zq1 = __fdividef(cq1, 1.0f + __expf(-cq1));
#pragma unroll
        for (int k = 0; k < 4; k++) {
            int ja = clampj(jq0 + k) * HD + l;
            int jb = clampj(jq1 + k) * HD + l + 32;
            zq0 = fmaf(wq0[k], Wc[ja] - mb[ja], zq0);
            zq1 = fmaf(wq1[k], Wc[jb] - mb[jb], zq1);
        }
        s1 = zq0 + zq1;
        s2 = fmaf(zq0, zq0, zq1 * zq1);
        wsum2(s1, s2);
        mu = s1 * (1.f / 64.f);
        var = s2 * (1.f / 64.f) - mu * mu;
        rstd = rsqrtf(var + EPSV);
        float y0 = cq0 + fmaf(g0, (zq0 - mu) * rstd, be0);
        float y1 = cq1 + fmaf(g1, (zq1 - mu) * rstd, be1);

        size_t yo = (size_t)(n * MB + m) * DIM;
        Yb[yo + l] = y0;
        Yb[yo + l + 32] = y1;

        if (tid < 176) {
            const float4 wv = *(const float4 *)(Wc + tid * 4);
            const float4 cv = *(const float4 *)(tokbuf + 15 * TPITCH + tid * 4);
            float4 r;
            r.x = wv.x - cv.x; r.y = wv.y - cv.y;
            r.z = wv.z - cv.z; r.w = wv.w - cv.w;
            *(float4 *)(Wn + tid * 4) = r;
        }
        __syncthreads();  // C -> A'
        cur ^= 1;
    }
}

// ---------------------------------------------------------------------------
// Final layernorm over DIM, in place on g_Y
// ---------------------------------------------------------------------------
__global__ __launch_bounds__(256) void ln_kernel(const float *__restrict__ pw,
                                                 const float *__restrict__ pb) {
    int row = blockIdx.x;
    int tid = threadIdx.x;
    float4 v = *((const float4 *)(g_Y + (size_t)row * 1024) + tid);
    float s1 = v.x + v.y + v.z + v.w;
    float s2 = v.x * v.x + v.y * v.y + v.z * v.z + v.w * v.w;
    wsum2(s1, s2);
    __shared__ float sa[8], sb[8];
    int w = tid >> 5, l = tid & 31;
    if (l == 0) { sa[w] = s1; sb[w] = s2; }
    __syncthreads();
    s1 = 0.f; s2 = 0.f;
#pragma unroll
    for (int i = 0; i < 8; i++) { s1 += sa[i]; s2 += sb[i]; }
    float mu = s1 * (1.f / 1024.f);
    float var = s2 * (1.f / 1024.f) - mu * mu;
    float rstd = rsqrtf(var + EPSV);
    float4 pwv = *((const float4 *)pw + tid);
    float4 pbv = *((const float4 *)pb + tid);
    float4 o;
    o.x = (v.x - mu) * rstd * pwv.x + pbv.x;
    o.y = (v.y - mu) * rstd * pwv.y + pbv.y;
    o.z = (v.z - mu) * rstd * pwv.z + pbv.z;
    o.w = (v.w - mu) * rstd * pwv.w + pbv.w;
    *((float4 *)(g_Y + (size_t)row * 1024) + tid) = o;
}

// ---------------------------------------------------------------------------
// Launch
// ---------------------------------------------------------------------------
extern "C" void kernel_launch(void *const *d_in, const int *in_sizes, int n_in,
                              void *d_out, int out_size) {
    const float *x     = (const float *)d_in[0];
    const float *posf  = (const float *)d_in[1];
    const float *Wq    = (const float *)d_in[2];
    const float *Wk    = (const float *)d_in[3];
    const float *Wv    = (const float *)d_in[4];
    const float *Wo    = (const float *)d_in[5];
    const float *lrW   = (const float *)d_in[6];
    const float *lrb   = (const float *)d_in[7];
    const float *gsc   = (const float *)d_in[8];
    const float *tgam  = (const float *)d_in[9];
    const float *tbet  = (const float *)d_in[10];
    const float *postw = (const float *)d_in[11];
    const float *postb = (const float *)d_in[12];
    const float *coeff = (const float *)d_in[13];
    const float *knots = (const float *)d_in[14];
    float *out = (float *)d_out;

    const int scan_smem = (MB * TPITCH + 2 * NB * HD) * sizeof(float);  // 54784 B
    cudaFuncSetAttribute(scan_kernel, cudaFuncAttributeMaxDynamicSharedMemorySize,
                         scan_smem);

    rope_tab_kernel<<<(SS * (HD / 2) + 1023) / 1024, 1024>>>(posf);
    tc_qkv_kernel<<<dim3(DIM / 128, BB * SS / 128, 3), 256>>>(x, Wq, Wk, Wv);
    eta_kernel<<<BB * SS, 128>>>(x, lrW, lrb, gsc);
    scan_kernel<<<BB * HH, 512, scan_smem>>>(tgam, tbet, knots, coeff);
    ln_kernel<<<BB * SS, 256>>>(postw, postb);
    tc_out_kernel<<<dim3(DIM / 128, BB * SS / 128, 1), 256>>>(Wo, out);
}